// round 10
// baseline (speedup 1.0000x reference)
#include <cuda_runtime.h>
#include <cuda_fp16.h>
#include <cstdint>

#define BATCH 64
#define HDIM 512
#define HH 262144      // HDIM*HDIM
#define NSEQ 2048
#define NFOCUS 256

// ---------------- scratch (static device globals; no runtime allocation) ----
__device__ float g_Y[(size_t)BATCH * HH];      // 64 MB (Yq then Yk)
__device__ float g_Qp[8 * BATCH * HDIM];
__device__ float g_Q[BATCH * HDIM];
__device__ float g_w[BATCH * HDIM];
__device__ float g_compat[BATCH * NSEQ];
__device__ int   g_idx[BATCH * NFOCUS];

// ======================= mma.sync helpers (HMMA path) =======================
__device__ __forceinline__ uint32_t smem_u32(const void* p) {
    uint32_t a;
    asm("{ .reg .u64 t; cvta.to.shared.u64 t, %1; cvt.u32.u64 %0, t; }"
        : "=r"(a) : "l"(p));
    return a;
}
__device__ __forceinline__ void ldsm4(uint32_t* r, uint32_t a) {
    asm volatile("ldmatrix.sync.aligned.m8n8.x4.shared.b16 {%0,%1,%2,%3}, [%4];"
                 : "=r"(r[0]), "=r"(r[1]), "=r"(r[2]), "=r"(r[3]) : "r"(a));
}
__device__ __forceinline__ void ldsm2(uint32_t* r, uint32_t a) {
    asm volatile("ldmatrix.sync.aligned.m8n8.x2.shared.b16 {%0,%1}, [%2];"
                 : "=r"(r[0]), "=r"(r[1]) : "r"(a));
}
__device__ __forceinline__ void mma16816(float* c, const uint32_t* a, const uint32_t* b) {
    asm volatile(
        "mma.sync.aligned.m16n8k16.row.col.f32.f16.f16.f32 "
        "{%0,%1,%2,%3}, {%4,%5,%6,%7}, {%8,%9}, {%0,%1,%2,%3};"
        : "+f"(c[0]), "+f"(c[1]), "+f"(c[2]), "+f"(c[3])
        : "r"(a[0]), "r"(a[1]), "r"(a[2]), "r"(a[3]), "r"(b[0]), "r"(b[1]));
}
// x ~= h1 + 2^-11 * h2  (h2 holds the residue scaled by 2^11 -> normal range)
__device__ __forceinline__ void split2h(float x, uint16_t& h1, uint16_t& h2) {
    __half a = __float2half_rn(x);
    float r = (x - __half2float(a)) * 2048.0f;
    __half b = __float2half_rn(r);
    h1 = __half_as_ushort(a);
    h2 = __half_as_ushort(b);
}
#define BAR_SYNC(id, cnt)   asm volatile("bar.sync %0, %1;"   :: "r"(id), "r"(cnt) : "memory")
#define BAR_ARRIVE(id, cnt) asm volatile("bar.arrive %0, %1;" :: "r"(id), "r"(cnt) : "memory")

// ========= emulated-fp32 GEMM via 2-way fp16 split (3 HMMA products) ========
// Warp-specialized: 8 consumer warps (32m x 32n tiles; ldsm+mma only) +
// 4 producer warps (W and X: LDG (reg double-buffer, 1 chunk ahead) ->
// convert -> STS fp16). 3-stage fp16 ring, named barriers, no cp.async.
#define KC 32                        // k per chunk
#define NCHUNK (HDIM / KC)           // 16
#define NTILE 128                    // n per CTA
#define THREADS 384
#define NCONS 256
#define ROWB 80                      // padded fp16 smem row bytes (64B + 16 pad)
// smem byte offsets:
#define FS(s)          ((s) * 30720u)
#define WS_OFF(s, l)   (FS(s) + (l) * 10240u)          // 128n x 32k fp16 (ROWB)
#define XS_OFF(s, l)   (FS(s) + 20480u + (l) * 5120u)  // 64b x 32k fp16 (ROWB)
#define SMEM_BYTES 92160
// named barriers: FULL_s = 1+s, EMPTY_s = 4+s (s=0..2)

__global__ __launch_bounds__(THREADS, 1) void gemm_mma(
    const float* __restrict__ X, const float* __restrict__ W,
    const float* __restrict__ bias)
{
    extern __shared__ __align__(16) char smem_raw[];
    const uint32_t sb = smem_u32(smem_raw);
    const int tid = threadIdx.x;
    const int wid = tid >> 5, lane = tid & 31;
    const int n0 = blockIdx.x * NTILE;

    if (wid < 8) {
        // ============ CONSUMERS: 32m x 32n per warp, ldsm + mma only ========
        const int mpair = wid & 1;
        const int nq    = wid >> 1;          // 0..3 (32 n each)

        float lo[2][4][4], hi[2][4][4];
        #pragma unroll
        for (int m = 0; m < 2; m++)
            #pragma unroll
            for (int j = 0; j < 4; j++)
                #pragma unroll
                for (int q = 0; q < 4; q++) { lo[m][j][q] = 0.f; hi[m][j][q] = 0.f; }

        const uint32_t a_row = (uint32_t)(32 * mpair + (lane & 15)) * ROWB + ((lane >> 4) << 4);
        const uint32_t b_row = (uint32_t)(nq * 32 + (lane & 7)) * ROWB + (((lane >> 3) & 1) << 4);

        for (int kc = 0; kc < NCHUNK; kc++) {
            const int s = kc % 3;
            BAR_SYNC(1 + s, THREADS);        // wait stage full

            #pragma unroll
            for (int ks = 0; ks < 2; ks++) {
                uint32_t b1[4][2], b2[4][2], a1[2][4], a2[2][4];
                #pragma unroll
                for (int j = 0; j < 4; j++) {
                    ldsm2(b1[j], sb + WS_OFF(s, 0) + b_row + (uint32_t)j * (8 * ROWB) + ks * 32);
                    ldsm2(b2[j], sb + WS_OFF(s, 1) + b_row + (uint32_t)j * (8 * ROWB) + ks * 32);
                }
                #pragma unroll
                for (int m = 0; m < 2; m++) {
                    ldsm4(a1[m], sb + XS_OFF(s, 0) + a_row + (uint32_t)m * (16 * ROWB) + ks * 32);
                    ldsm4(a2[m], sb + XS_OFF(s, 1) + a_row + (uint32_t)m * (16 * ROWB) + ks * 32);
                }
                #pragma unroll
                for (int m = 0; m < 2; m++)
                    #pragma unroll
                    for (int j = 0; j < 4; j++) mma16816(lo[m][j], a1[m], b1[j]);
                #pragma unroll
                for (int m = 0; m < 2; m++)
                    #pragma unroll
                    for (int j = 0; j < 4; j++) mma16816(hi[m][j], a1[m], b2[j]);
                #pragma unroll
                for (int m = 0; m < 2; m++)
                    #pragma unroll
                    for (int j = 0; j < 4; j++) mma16816(hi[m][j], a2[m], b1[j]);
            }

            BAR_ARRIVE(4 + s, THREADS);      // signal stage empty
        }

        // ---- epilogue: Y = lo + hi/2048 + bias ----
        const float sc = 1.0f / 2048.0f;
        const int ncol = n0 + nq * 32 + (lane & 3) * 2;
        #pragma unroll
        for (int m = 0; m < 2; m++) {
            const int brow = 32 * mpair + 16 * m + (lane >> 2);
            #pragma unroll
            for (int j = 0; j < 4; j++) {
                const int n = ncol + j * 8;
                const float2 bz = *(const float2*)&bias[n];
                float2 o0 = make_float2(fmaf(hi[m][j][0], sc, lo[m][j][0]) + bz.x,
                                        fmaf(hi[m][j][1], sc, lo[m][j][1]) + bz.y);
                float2 o1 = make_float2(fmaf(hi[m][j][2], sc, lo[m][j][2]) + bz.x,
                                        fmaf(hi[m][j][3], sc, lo[m][j][3]) + bz.y);
                *(float2*)&g_Y[(size_t)brow * HH + n]       = o0;
                *(float2*)&g_Y[(size_t)(brow + 8) * HH + n] = o1;
            }
        }
    } else {
        // ======== PRODUCERS: LDG (1 chunk ahead) -> convert -> STS fp16 =====
        const int ptid = tid - NCONS;                 // 0..127
        const int n4  = ptid & 31;                    // 4 consecutive n
        const int kg  = ptid >> 5;                    // k-octet (0..3)
        const int xb  = ptid >> 1, xkh = ptid & 1;    // X mapping

        float4 wbufA[8], wbufB[8], xbufA[4], xbufB[4];

        #define WLOAD(dst, chunk) do {                                          \
            const float* wsrc = W + (size_t)((chunk) * KC + kg * 8) * HH        \
                                + n0 + n4 * 4;                                  \
            _Pragma("unroll")                                                   \
            for (int i = 0; i < 8; i++)                                         \
                dst[i] = __ldcs((const float4*)(wsrc + (size_t)i * HH));        \
        } while (0)

        #define XLOAD(dst, chunk) do {                                          \
            const float* xsrc = X + (size_t)xb * HDIM + (chunk) * KC + xkh * 16;\
            _Pragma("unroll")                                                   \
            for (int i = 0; i < 4; i++)                                         \
                dst[i] = __ldg((const float4*)(xsrc + i * 4));                  \
        } while (0)

        #define WCONVERT(src, s) do {                                           \
            _Pragma("unroll")                                                   \
            for (int j = 0; j < 4; j++) {                                       \
                uint32_t u1[4], u2[4];                                          \
                _Pragma("unroll")                                               \
                for (int p = 0; p < 4; p++) {                                   \
                    float x0 = ((const float*)&src[2 * p])[j];                  \
                    float x1 = ((const float*)&src[2 * p + 1])[j];              \
                    uint16_t a1v, a2v, c1v, c2v;                                \
                    split2h(x0, a1v, a2v);                                      \
                    split2h(x1, c1v, c2v);                                      \
                    u1[p] = (uint32_t)a1v | ((uint32_t)c1v << 16);              \
                    u2[p] = (uint32_t)a2v | ((uint32_t)c2v << 16);              \
                }                                                               \
                const uint32_t rb = (uint32_t)(n4 * 4 + j) * ROWB + kg * 16;    \
                asm volatile("st.shared.v4.b32 [%0], {%1,%2,%3,%4};" ::         \
                    "r"(sb + WS_OFF(s, 0) + rb),                                \
                    "r"(u1[0]), "r"(u1[1]), "r"(u1[2]), "r"(u1[3]) : "memory"); \
                asm volatile("st.shared.v4.b32 [%0], {%1,%2,%3,%4};" ::         \
                    "r"(sb + WS_OFF(s, 1) + rb),                                \
                    "r"(u2[0]), "r"(u2[1]), "r"(u2[2]), "r"(u2[3]) : "memory"); \
            }                                                                   \
        } while (0)

        #define XCONVERT(src, s) do {                                           \
            uint32_t v1[8], v2[8];                                              \
            _Pragma("unroll")                                                   \
            for (int i = 0; i < 4; i++) {                                       \
                float4 xv = src[i];                                             \
                uint16_t a1v, a2v, c1v, c2v;                                    \
                split2h(xv.x, a1v, a2v); split2h(xv.y, c1v, c2v);               \
                v1[i*2]   = (uint32_t)a1v | ((uint32_t)c1v << 16);              \
                v2[i*2]   = (uint32_t)a2v | ((uint32_t)c2v << 16);              \
                split2h(xv.z, a1v, a2v); split2h(xv.w, c1v, c2v);               \
                v1[i*2+1] = (uint32_t)a1v | ((uint32_t)c1v << 16);              \
                v2[i*2+1] = (uint32_t)a2v | ((uint32_t)c2v << 16);              \
            }                                                                   \
            const uint32_t xrb = (uint32_t)xb * ROWB + xkh * 32;                \
            asm volatile("st.shared.v4.b32 [%0], {%1,%2,%3,%4};" ::             \
                "r"(sb + XS_OFF(s, 0) + xrb),                                   \
                "r"(v1[0]), "r"(v1[1]), "r"(v1[2]), "r"(v1[3]) : "memory");     \
            asm volatile("st.shared.v4.b32 [%0], {%1,%2,%3,%4};" ::             \
                "r"(sb + XS_OFF(s, 0) + xrb + 16),                              \
                "r"(v1[4]), "r"(v1[5]), "r"(v1[6]), "r"(v1[7]) : "memory");     \
            asm volatile("st.shared.v4.b32 [%0], {%1,%2,%3,%4};" ::             \
                "r"(sb + XS_OFF(s, 1) + xrb),                                   \
                "r"(v2[0]), "r"(v2[1]), "r"(v2[2]), "r"(v2[3]) : "memory");     \
            asm volatile("st.shared.v4.b32 [%0], {%1,%2,%3,%4};" ::             \
                "r"(sb + XS_OFF(s, 1) + xrb + 16),                              \
                "r"(v2[4]), "r"(v2[5]), "r"(v2[6]), "r"(v2[7]) : "memory");     \
        } while (0)

        WLOAD(wbufA, 0);
        XLOAD(xbufA, 0);

        for (int kc = 0; kc < NCHUNK; kc++) {
            // prefetch next chunk into the other register buffer
            if (kc + 1 < NCHUNK) {
                if (kc & 1) { WLOAD(wbufA, kc + 1); XLOAD(xbufA, kc + 1); }
                else        { WLOAD(wbufB, kc + 1); XLOAD(xbufB, kc + 1); }
            }

            const int s = kc % 3;
            if (kc >= 3) BAR_SYNC(4 + s, THREADS);   // wait stage empty

            if (kc & 1) { WCONVERT(wbufB, s); XCONVERT(xbufB, s); }
            else        { WCONVERT(wbufA, s); XCONVERT(xbufA, s); }

            asm volatile("membar.cta;" ::: "memory");  // STS visible before arrive
            BAR_ARRIVE(1 + s, THREADS);      // signal stage full
        }
        #undef WLOAD
        #undef XLOAD
        #undef WCONVERT
        #undef XCONVERT
    }
}

// ---------------- Qpart[s,b,k] = sum_{h in slice s} x[b,h] * Y[b, h*H + k] --
__global__ void contract_q(const float* __restrict__ X) {
    const int b = blockIdx.y, s = blockIdx.x;
    const int k = threadIdx.x;  // 512
    __shared__ float xs[64];
    if (k < 64) xs[k] = X[b * HDIM + s * 64 + k];
    __syncthreads();
    const float* Yb = g_Y + (size_t)b * HH + (size_t)s * 64 * HDIM + k;
    float a0 = 0.f, a1 = 0.f, a2 = 0.f, a3 = 0.f;
    #pragma unroll
    for (int hh = 0; hh < 64; hh += 4) {
        a0 = fmaf(xs[hh + 0], Yb[(hh + 0) * HDIM], a0);
        a1 = fmaf(xs[hh + 1], Yb[(hh + 1) * HDIM], a1);
        a2 = fmaf(xs[hh + 2], Yb[(hh + 2) * HDIM], a2);
        a3 = fmaf(xs[hh + 3], Yb[(hh + 3) * HDIM], a3);
    }
    g_Qp[(s * BATCH + b) * HDIM + k] = (a0 + a1) + (a2 + a3);
}

__global__ void reduce_q() {
    const int b = blockIdx.x, k = threadIdx.x;
    float v = 0.f;
    #pragma unroll
    for (int s = 0; s < 8; s++) v += g_Qp[(s * BATCH + b) * HDIM + k];
    g_Q[b * HDIM + k] = v;
}

// ---------------- w[b,h] = < Y[b, h*H : h*H+H] , Q[b,:] > -------------------
__global__ void contract_w() {
    const int b = blockIdx.y;
    const int warp = threadIdx.x >> 5, lane = threadIdx.x & 31;
    const int h = blockIdx.x * 8 + warp;
    __shared__ float qs[HDIM];
    for (int i = threadIdx.x; i < HDIM; i += 256) qs[i] = g_Q[b * HDIM + i];
    __syncthreads();
    const float* Yb = g_Y + (size_t)b * HH + (size_t)h * HDIM;
    float acc = 0.f;
    #pragma unroll
    for (int s2 = 0; s2 < 4; s2++) {
        const int i4 = lane + s2 * 32;
        float4 y = *(const float4*)&Yb[i4 * 4];
        float4 q = *(const float4*)&qs[i4 * 4];
        acc += y.x * q.x + y.y * q.y + y.z * q.z + y.w * q.w;
    }
    #pragma unroll
    for (int off = 16; off; off >>= 1) acc += __shfl_xor_sync(~0u, acc, off);
    if (lane == 0) g_w[b * HDIM + h] = acc;
}

// ---------------- compat[b,n] = norm * < ve[b,n,:], w[b,:] > ----------------
__global__ void compat_k(const float* __restrict__ ve) {
    const int b = blockIdx.y;
    const int warp = threadIdx.x >> 5, lane = threadIdx.x & 31;
    const int n = blockIdx.x * 8 + warp;
    __shared__ float ws[HDIM];
    for (int i = threadIdx.x; i < HDIM; i += 256) ws[i] = g_w[b * HDIM + i];
    __syncthreads();
    const float* v = ve + ((size_t)b * NSEQ + n) * HDIM;
    float acc = 0.f;
    #pragma unroll
    for (int s2 = 0; s2 < 4; s2++) {
        const int i4 = lane + s2 * 32;
        float4 y = *(const float4*)&v[i4 * 4];
        float4 q = *(const float4*)&ws[i4 * 4];
        acc += y.x * q.x + y.y * q.y + y.z * q.z + y.w * q.w;
    }
    #pragma unroll
    for (int off = 16; off; off >>= 1) acc += __shfl_xor_sync(~0u, acc, off);
    if (lane == 0) g_compat[b * NSEQ + n] = acc * 0.04419417382415922f;
}

// ---------------- per-batch ranking with fp32-exp flush boundary ------------
__global__ __launch_bounds__(1024) void topk_k() {
    __shared__ unsigned sk[NSEQ];
    __shared__ int      si[NSEQ];
    __shared__ float    redf[32];
    const int b = blockIdx.x, t = threadIdx.x;
    const int lane = t & 31, warp = t >> 5;

    const float c0 = g_compat[b * NSEQ + t];
    const float c1 = g_compat[b * NSEQ + t + 1024];

    float m = fmaxf(c0, c1);
    #pragma unroll
    for (int o = 16; o; o >>= 1) m = fmaxf(m, __shfl_xor_sync(~0u, m, o));
    if (lane == 0) redf[warp] = m;
    __syncthreads();
    float mx = redf[0];
    #pragma unroll
    for (int i = 1; i < 32; i++) mx = fmaxf(mx, redf[i]);

    auto mkkey = [&](float c) -> unsigned {
        float d = c - mx;
        if (d < -87.33654785f) return 0u;
        unsigned u = __float_as_uint(c);
        return (u & 0x80000000u) ? ~u : (u | 0x80000000u);
    };
    sk[t]        = mkkey(c0);  si[t]        = t;
    sk[t + 1024] = mkkey(c1);  si[t + 1024] = t + 1024;

    for (int k = 2; k <= NSEQ; k <<= 1) {
        for (int j = k >> 1; j > 0; j >>= 1) {
            __syncthreads();
            #pragma unroll
            for (int half = 0; half < 2; half++) {
                const int i = half * 1024 + t;
                const int ixj = i ^ j;
                if (ixj > i) {
                    const bool desc = ((i & k) == 0);
                    unsigned ki = sk[i], kj = sk[ixj];
                    int      ii = si[i], ij = si[ixj];
                    const bool jBeforeI = (kj > ki) || (kj == ki && ij < ii);
                    if (desc ? jBeforeI : !jBeforeI) {
                        sk[i] = kj; sk[ixj] = ki;
                        si[i] = ij; si[ixj] = ii;
                    }
                }
            }
        }
    }
    __syncthreads();
    if (t < NFOCUS) g_idx[b * NFOCUS + t] = si[t];
}

// ---------------- gather: out[b,r,:] = ve[b, idx[b,r], :] -------------------
__global__ void gather_k(const float* __restrict__ ve, float* __restrict__ out) {
    const int b = blockIdx.y, r = blockIdx.x;
    const int idx = g_idx[b * NFOCUS + r];
    const float4* src = (const float4*)(ve + ((size_t)b * NSEQ + idx) * HDIM);
    float4* dst = (float4*)(out + ((size_t)b * NFOCUS + r) * HDIM);
    dst[threadIdx.x] = src[threadIdx.x];
}

// ---------------- launch ----------------------------------------------------
extern "C" void kernel_launch(void* const* d_in, const int* in_sizes, int n_in,
                              void* d_out, int out_size) {
    const float* vs = (const float*)d_in[0];   // (64, 1, 512)
    const float* ve = (const float*)d_in[1];   // (64, 2048, 512)
    const float* Wq = (const float*)d_in[2];   // (512, 262144)
    const float* bq = (const float*)d_in[3];   // (262144,)
    const float* Wk = (const float*)d_in[4];   // (512, 262144)
    const float* bk = (const float*)d_in[5];   // (262144,)
    float* out = (float*)d_out;                // (64, 256, 512)

    cudaFuncSetAttribute(gemm_mma, cudaFuncAttributeMaxDynamicSharedMemorySize, SMEM_BYTES);

    gemm_mma<<<HH / NTILE, THREADS, SMEM_BYTES>>>(vs, Wq, bq);
    contract_q<<<dim3(8, BATCH), 512>>>(vs);
    reduce_q<<<BATCH, HDIM>>>();

    gemm_mma<<<HH / NTILE, THREADS, SMEM_BYTES>>>(vs, Wk, bk);
    contract_w<<<dim3(64, BATCH), 256>>>();

    compat_k<<<dim3(NSEQ / 8, BATCH), 256>>>(ve);
    topk_k<<<BATCH, 1024>>>();
    gather_k<<<dim3(NFOCUS, BATCH), 128>>>(ve, out);
}

// round 11
// speedup vs baseline: 1.2711x; 1.2711x over previous
#include <cuda_runtime.h>
#include <cuda_fp16.h>
#include <cstdint>

#define BATCH 64
#define HDIM 512
#define HH 262144      // HDIM*HDIM
#define NSEQ 2048
#define NFOCUS 256

// ---------------- scratch (static device globals; no runtime allocation) ----
__device__ float g_Y[(size_t)BATCH * HH];      // 64 MB (Yq then Yk)
__device__ float g_Qp[8 * BATCH * HDIM];
__device__ float g_Q[BATCH * HDIM];
__device__ float g_w[BATCH * HDIM];
__device__ float g_compat[BATCH * NSEQ];
__device__ int   g_idx[BATCH * NFOCUS];

// ======================= mma.sync helpers (HMMA path) =======================
__device__ __forceinline__ uint32_t smem_u32(const void* p) {
    uint32_t a;
    asm("{ .reg .u64 t; cvta.to.shared.u64 t, %1; cvt.u32.u64 %0, t; }"
        : "=r"(a) : "l"(p));
    return a;
}
__device__ __forceinline__ void ldsm4(uint32_t* r, uint32_t a) {
    asm volatile("ldmatrix.sync.aligned.m8n8.x4.shared.b16 {%0,%1,%2,%3}, [%4];"
                 : "=r"(r[0]), "=r"(r[1]), "=r"(r[2]), "=r"(r[3]) : "r"(a));
}
__device__ __forceinline__ void ldsm2(uint32_t* r, uint32_t a) {
    asm volatile("ldmatrix.sync.aligned.m8n8.x2.shared.b16 {%0,%1}, [%2];"
                 : "=r"(r[0]), "=r"(r[1]) : "r"(a));
}
__device__ __forceinline__ void mma16816(float* c, const uint32_t* a, const uint32_t* b) {
    asm volatile(
        "mma.sync.aligned.m16n8k16.row.col.f32.f16.f16.f32 "
        "{%0,%1,%2,%3}, {%4,%5,%6,%7}, {%8,%9}, {%0,%1,%2,%3};"
        : "+f"(c[0]), "+f"(c[1]), "+f"(c[2]), "+f"(c[3])
        : "r"(a[0]), "r"(a[1]), "r"(a[2]), "r"(a[3]), "r"(b[0]), "r"(b[1]));
}
// Split a PAIR of fp32 into two packed fp16 levels with only 2 cvt instrs.
// t = float(RN-fp16(x)) computed in ALU (bit trick, exact RN-even match);
// r = (x - t) * 2048 (residual scaled into fp16 normal range).
// uA = pack(h(t0), h(t1)) (lo = elem0), uB = pack(h(r0), h(r1)).
__device__ __forceinline__ void split_pair(float x0, float x1,
                                           uint32_t& uA, uint32_t& uB) {
    uint32_t b0 = __float_as_uint(x0), b1 = __float_as_uint(x1);
    float t0 = __uint_as_float((b0 + 0xFFFu + ((b0 >> 13) & 1u)) & 0xFFFFE000u);
    float t1 = __uint_as_float((b1 + 0xFFFu + ((b1 >> 13) & 1u)) & 0xFFFFE000u);
    float r0 = (x0 - t0) * 2048.0f;
    float r1 = (x1 - t1) * 2048.0f;
    asm("cvt.rn.f16x2.f32 %0, %1, %2;" : "=r"(uA) : "f"(t1), "f"(t0));
    asm("cvt.rn.f16x2.f32 %0, %1, %2;" : "=r"(uB) : "f"(r1), "f"(r0));
}
__device__ __forceinline__ void cp16(uint32_t dst, const void* src) {
    asm volatile("cp.async.cg.shared.global [%0], [%1], 16;"
                 :: "r"(dst), "l"(src) : "memory");
}
#define CP_COMMIT() asm volatile("cp.async.commit_group;" ::: "memory")

// ========= emulated-fp32 GEMM via 2-way fp16 split (3 HMMA products) ========
// Round-7 structure: cp.async 4-stage raw pipeline + per-chunk BSP sync.
// Only change: split2h -> split_pair (ALU split + packed cvt).
#define KC 32                        // k per chunk
#define NCHUNK (HDIM / KC)           // 16
#define NTILE 128                    // n per CTA
#define THREADS 512
#define ROWB 80                      // padded fp16 smem row bytes (64B + 16 pad)
// smem byte offsets:
#define RAWW_OFF(st)      ((st) * 16384u)                     // 32k x 128n fp32
#define RAWX_OFF(st)      (65536u + (st) * 8192u)             // 64b x 32k fp32
#define WS_OFF(buf, lvl)  (98304u + (buf) * 20480u + (lvl) * 10240u)
#define XS_OFF(buf, lvl)  (139264u + (buf) * 10240u + (lvl) * 5120u)
#define SMEM_BYTES 159744

__global__ __launch_bounds__(THREADS, 1) void gemm_mma(
    const float* __restrict__ X, const float* __restrict__ W,
    const float* __restrict__ bias)
{
    extern __shared__ __align__(16) char smem_raw[];
    const uint32_t sb = smem_u32(smem_raw);
    const int tid = threadIdx.x;
    const int wid = tid >> 5, lane = tid & 31;
    const int n0 = blockIdx.x * NTILE;

    // warp tile: 32 batches (mpair) x 16 n (noct)
    const int mpair = wid & 1;
    const int noct  = wid >> 1;          // 0..7

    float lo[2][2][4], hi[2][2][4];
    #pragma unroll
    for (int m = 0; m < 2; m++)
        #pragma unroll
        for (int j = 0; j < 2; j++)
            #pragma unroll
            for (int q = 0; q < 4; q++) { lo[m][j][q] = 0.f; hi[m][j][q] = 0.f; }

    // converter mappings
    const int wn = tid & 127, wkh = tid >> 7;     // W: n col, k-octet (0..3)
    const int xb = tid >> 3, xq = tid & 7;        // X: batch row, k-quad

    // fragment smem base offsets
    const uint32_t a_row = (uint32_t)(32 * mpair + (lane & 15)) * ROWB + ((lane >> 4) << 4);
    const uint32_t b_row = (uint32_t)(noct * 16 + (lane & 7)) * ROWB + (((lane >> 3) & 1) << 4);

    // producer segment mapping for cp.async (W: 1024 16B-segs, 2 per thread)
    const int segk0 = tid >> 5, segn = tid & 31;  // seg t: k=segk0, n-off=segn*16B

    #define ISSUE_STAGE(stg, chunk) do {                                         \
        const uint32_t wdst = sb + RAWW_OFF(stg);                                \
        const float* wsrc = W + (size_t)((chunk) * KC) * HH + n0;                \
        cp16(wdst + (uint32_t)segk0 * 512u + (uint32_t)segn * 16u,               \
             wsrc + (size_t)segk0 * HH + segn * 4);                              \
        cp16(wdst + (uint32_t)(segk0 + 16) * 512u + (uint32_t)segn * 16u,        \
             wsrc + (size_t)(segk0 + 16) * HH + segn * 4);                       \
        cp16(sb + RAWX_OFF(stg) + (uint32_t)xb * 128u + (uint32_t)xq * 16u,      \
             X + (size_t)xb * HDIM + (chunk) * KC + xq * 4);                     \
        CP_COMMIT();                                                             \
    } while (0)

    #define CONVERT_STAGE(stg, buf) do {                                         \
        const char* rw = smem_raw + RAWW_OFF(stg);                               \
        float wv[8];                                                             \
        _Pragma("unroll")                                                        \
        for (int j = 0; j < 8; j++)                                              \
            wv[j] = *(const float*)(rw + (uint32_t)(wkh * 8 + j) * 512u + (uint32_t)wn * 4u); \
        uint32_t u1[4], u2[4];                                                   \
        _Pragma("unroll")                                                        \
        for (int p = 0; p < 4; p++)                                              \
            split_pair(wv[2 * p], wv[2 * p + 1], u1[p], u2[p]);                  \
        const uint32_t rb = (uint32_t)wn * ROWB + wkh * 16;                      \
        asm volatile("st.shared.v4.b32 [%0], {%1,%2,%3,%4};" ::                  \
            "r"(sb + WS_OFF(buf, 0) + rb), "r"(u1[0]), "r"(u1[1]), "r"(u1[2]), "r"(u1[3]) : "memory"); \
        asm volatile("st.shared.v4.b32 [%0], {%1,%2,%3,%4};" ::                  \
            "r"(sb + WS_OFF(buf, 1) + rb), "r"(u2[0]), "r"(u2[1]), "r"(u2[2]), "r"(u2[3]) : "memory"); \
        float4 xv = *(const float4*)(smem_raw + RAWX_OFF(stg) + (uint32_t)xb * 128u + (uint32_t)xq * 16u); \
        uint32_t v1[2], v2[2];                                                   \
        split_pair(xv.x, xv.y, v1[0], v2[0]);                                    \
        split_pair(xv.z, xv.w, v1[1], v2[1]);                                    \
        const uint32_t xrb = (uint32_t)xb * ROWB + xq * 8;                       \
        asm volatile("st.shared.v2.b32 [%0], {%1,%2};" ::                        \
            "r"(sb + XS_OFF(buf, 0) + xrb), "r"(v1[0]), "r"(v1[1]) : "memory");  \
        asm volatile("st.shared.v2.b32 [%0], {%1,%2};" ::                        \
            "r"(sb + XS_OFF(buf, 1) + xrb), "r"(v2[0]), "r"(v2[1]) : "memory");  \
    } while (0)

    // ---- prologue: stages 0..2 in flight; convert chunk 0 ----
    ISSUE_STAGE(0, 0);
    ISSUE_STAGE(1, 1);
    ISSUE_STAGE(2, 2);
    asm volatile("cp.async.wait_group 2;" ::: "memory");
    __syncthreads();
    CONVERT_STAGE(0, 0);

    for (int kc = 0; kc < NCHUNK; kc++) {
        const int cur = kc & 1;

        if (kc + 3 < NCHUNK) ISSUE_STAGE((kc + 3) & 3, kc + 3);

        if (kc + 1 < NCHUNK) {
            if (kc < NCHUNK - 3)      asm volatile("cp.async.wait_group 2;" ::: "memory");
            else if (kc == NCHUNK - 3) asm volatile("cp.async.wait_group 1;" ::: "memory");
            else                       asm volatile("cp.async.wait_group 0;" ::: "memory");
        }
        __syncthreads();

        if (kc + 1 < NCHUNK) CONVERT_STAGE((kc + 1) & 3, (kc + 1) & 1);

        // ---- mma on current fp16 buffer ----
        #pragma unroll
        for (int ks = 0; ks < 2; ks++) {
            uint32_t b1[2][2], b2[2][2], a1[2][4], a2[2][4];
            #pragma unroll
            for (int j = 0; j < 2; j++) {
                ldsm2(b1[j], sb + WS_OFF(cur, 0) + b_row + (uint32_t)j * (8 * ROWB) + ks * 32);
                ldsm2(b2[j], sb + WS_OFF(cur, 1) + b_row + (uint32_t)j * (8 * ROWB) + ks * 32);
            }
            #pragma unroll
            for (int m = 0; m < 2; m++) {
                ldsm4(a1[m], sb + XS_OFF(cur, 0) + a_row + (uint32_t)m * (16 * ROWB) + ks * 32);
                ldsm4(a2[m], sb + XS_OFF(cur, 1) + a_row + (uint32_t)m * (16 * ROWB) + ks * 32);
            }
            #pragma unroll
            for (int m = 0; m < 2; m++)
                #pragma unroll
                for (int j = 0; j < 2; j++) mma16816(lo[m][j], a1[m], b1[j]);
            #pragma unroll
            for (int m = 0; m < 2; m++)
                #pragma unroll
                for (int j = 0; j < 2; j++) mma16816(hi[m][j], a1[m], b2[j]);
            #pragma unroll
            for (int m = 0; m < 2; m++)
                #pragma unroll
                for (int j = 0; j < 2; j++) mma16816(hi[m][j], a2[m], b1[j]);
        }
    }

    // ---- epilogue: Y = lo + hi/2048 + bias ----
    const float s = 1.0f / 2048.0f;
    const int ncol = n0 + noct * 16 + (lane & 3) * 2;
    #pragma unroll
    for (int m = 0; m < 2; m++) {
        const int brow = 32 * mpair + 16 * m + (lane >> 2);
        #pragma unroll
        for (int j = 0; j < 2; j++) {
            const int n = ncol + j * 8;
            const float2 bz = *(const float2*)&bias[n];
            float2 o0 = make_float2(fmaf(hi[m][j][0], s, lo[m][j][0]) + bz.x,
                                    fmaf(hi[m][j][1], s, lo[m][j][1]) + bz.y);
            float2 o1 = make_float2(fmaf(hi[m][j][2], s, lo[m][j][2]) + bz.x,
                                    fmaf(hi[m][j][3], s, lo[m][j][3]) + bz.y);
            *(float2*)&g_Y[(size_t)brow * HH + n]       = o0;
            *(float2*)&g_Y[(size_t)(brow + 8) * HH + n] = o1;
        }
    }
    #undef ISSUE_STAGE
    #undef CONVERT_STAGE
}

// ---------------- Qpart[s,b,k] = sum_{h in slice s} x[b,h] * Y[b, h*H + k] --
__global__ void contract_q(const float* __restrict__ X) {
    const int b = blockIdx.y, s = blockIdx.x;
    const int k = threadIdx.x;  // 512
    __shared__ float xs[64];
    if (k < 64) xs[k] = X[b * HDIM + s * 64 + k];
    __syncthreads();
    const float* Yb = g_Y + (size_t)b * HH + (size_t)s * 64 * HDIM + k;
    float a0 = 0.f, a1 = 0.f, a2 = 0.f, a3 = 0.f;
    #pragma unroll
    for (int hh = 0; hh < 64; hh += 4) {
        a0 = fmaf(xs[hh + 0], Yb[(hh + 0) * HDIM], a0);
        a1 = fmaf(xs[hh + 1], Yb[(hh + 1) * HDIM], a1);
        a2 = fmaf(xs[hh + 2], Yb[(hh + 2) * HDIM], a2);
        a3 = fmaf(xs[hh + 3], Yb[(hh + 3) * HDIM], a3);
    }
    g_Qp[(s * BATCH + b) * HDIM + k] = (a0 + a1) + (a2 + a3);
}

__global__ void reduce_q() {
    const int b = blockIdx.x, k = threadIdx.x;
    float v = 0.f;
    #pragma unroll
    for (int s = 0; s < 8; s++) v += g_Qp[(s * BATCH + b) * HDIM + k];
    g_Q[b * HDIM + k] = v;
}

// ---------------- w[b,h] = < Y[b, h*H : h*H+H] , Q[b,:] > -------------------
__global__ void contract_w() {
    const int b = blockIdx.y;
    const int warp = threadIdx.x >> 5, lane = threadIdx.x & 31;
    const int h = blockIdx.x * 8 + warp;
    __shared__ float qs[HDIM];
    for (int i = threadIdx.x; i < HDIM; i += 256) qs[i] = g_Q[b * HDIM + i];
    __syncthreads();
    const float* Yb = g_Y + (size_t)b * HH + (size_t)h * HDIM;
    float acc = 0.f;
    #pragma unroll
    for (int s2 = 0; s2 < 4; s2++) {
        const int i4 = lane + s2 * 32;
        float4 y = *(const float4*)&Yb[i4 * 4];
        float4 q = *(const float4*)&qs[i4 * 4];
        acc += y.x * q.x + y.y * q.y + y.z * q.z + y.w * q.w;
    }
    #pragma unroll
    for (int off = 16; off; off >>= 1) acc += __shfl_xor_sync(~0u, acc, off);
    if (lane == 0) g_w[b * HDIM + h] = acc;
}

// ---------------- compat[b,n] = norm * < ve[b,n,:], w[b,:] > ----------------
__global__ void compat_k(const float* __restrict__ ve) {
    const int b = blockIdx.y;
    const int warp = threadIdx.x >> 5, lane = threadIdx.x & 31;
    const int n = blockIdx.x * 8 + warp;
    __shared__ float ws[HDIM];
    for (int i = threadIdx.x; i < HDIM; i += 256) ws[i] = g_w[b * HDIM + i];
    __syncthreads();
    const float* v = ve + ((size_t)b * NSEQ + n) * HDIM;
    float acc = 0.f;
    #pragma unroll
    for (int s2 = 0; s2 < 4; s2++) {
        const int i4 = lane + s2 * 32;
        float4 y = *(const float4*)&v[i4 * 4];
        float4 q = *(const float4*)&ws[i4 * 4];
        acc += y.x * q.x + y.y * q.y + y.z * q.z + y.w * q.w;
    }
    #pragma unroll
    for (int off = 16; off; off >>= 1) acc += __shfl_xor_sync(~0u, acc, off);
    if (lane == 0) g_compat[b * NSEQ + n] = acc * 0.04419417382415922f;
}

// ---------------- per-batch ranking with fp32-exp flush boundary ------------
__global__ __launch_bounds__(1024) void topk_k() {
    __shared__ unsigned sk[NSEQ];
    __shared__ int      si[NSEQ];
    __shared__ float    redf[32];
    const int b = blockIdx.x, t = threadIdx.x;
    const int lane = t & 31, warp = t >> 5;

    const float c0 = g_compat[b * NSEQ + t];
    const float c1 = g_compat[b * NSEQ + t + 1024];

    float m = fmaxf(c0, c1);
    #pragma unroll
    for (int o = 16; o; o >>= 1) m = fmaxf(m, __shfl_xor_sync(~0u, m, o));
    if (lane == 0) redf[warp] = m;
    __syncthreads();
    float mx = redf[0];
    #pragma unroll
    for (int i = 1; i < 32; i++) mx = fmaxf(mx, redf[i]);

    auto mkkey = [&](float c) -> unsigned {
        float d = c - mx;
        if (d < -87.33654785f) return 0u;
        unsigned u = __float_as_uint(c);
        return (u & 0x80000000u) ? ~u : (u | 0x80000000u);
    };
    sk[t]        = mkkey(c0);  si[t]        = t;
    sk[t + 1024] = mkkey(c1);  si[t + 1024] = t + 1024;

    for (int k = 2; k <= NSEQ; k <<= 1) {
        for (int j = k >> 1; j > 0; j >>= 1) {
            __syncthreads();
            #pragma unroll
            for (int half = 0; half < 2; half++) {
                const int i = half * 1024 + t;
                const int ixj = i ^ j;
                if (ixj > i) {
                    const bool desc = ((i & k) == 0);
                    unsigned ki = sk[i], kj = sk[ixj];
                    int      ii = si[i], ij = si[ixj];
                    const bool jBeforeI = (kj > ki) || (kj == ki && ij < ii);
                    if (desc ? jBeforeI : !jBeforeI) {
                        sk[i] = kj; sk[ixj] = ki;
                        si[i] = ij; si[ixj] = ii;
                    }
                }
            }
        }
    }
    __syncthreads();
    if (t < NFOCUS) g_idx[b * NFOCUS + t] = si[t];
}

// ---------------- gather: out[b,r,:] = ve[b, idx[b,r], :] -------------------
__global__ void gather_k(const float* __restrict__ ve, float* __restrict__ out) {
    const int b = blockIdx.y, r = blockIdx.x;
    const int idx = g_idx[b * NFOCUS + r];
    const float4* src = (const float4*)(ve + ((size_t)b * NSEQ + idx) * HDIM);
    float4* dst = (float4*)(out + ((size_t)b * NFOCUS + r) * HDIM);
    dst[threadIdx.x] = src[threadIdx.x];
}

// ---------------- launch ----------------------------------------------------
extern "C" void kernel_launch(void* const* d_in, const int* in_sizes, int n_in,
                              void* d_out, int out_size) {
    const float* vs = (const float*)d_in[0];   // (64, 1, 512)
    const float* ve = (const float*)d_in[1];   // (64, 2048, 512)
    const float* Wq = (const float*)d_in[2];   // (512, 262144)
    const float* bq = (const float*)d_in[3];   // (262144,)
    const float* Wk = (const float*)d_in[4];   // (512, 262144)
    const float* bk = (const float*)d_in[5];   // (262144,)
    float* out = (float*)d_out;                // (64, 256, 512)

    cudaFuncSetAttribute(gemm_mma, cudaFuncAttributeMaxDynamicSharedMemorySize, SMEM_BYTES);

    gemm_mma<<<HH / NTILE, THREADS, SMEM_BYTES>>>(vs, Wq, bq);
    contract_q<<<dim3(8, BATCH), 512>>>(vs);
    reduce_q<<<BATCH, HDIM>>>();

    gemm_mma<<<HH / NTILE, THREADS, SMEM_BYTES>>>(vs, Wk, bk);
    contract_w<<<dim3(64, BATCH), 256>>>();

    compat_k<<<dim3(NSEQ / 8, BATCH), 256>>>(ve);
    topk_k<<<BATCH, 1024>>>();
    gather_k<<<dim3(NFOCUS, BATCH), 128>>>(ve, out);
}

// round 12
// speedup vs baseline: 1.4310x; 1.1258x over previous
#include <cuda_runtime.h>
#include <cuda_fp16.h>
#include <cstdint>

#define BATCH 64
#define HDIM 512
#define HH 262144      // HDIM*HDIM
#define NSEQ 2048
#define NFOCUS 256

// ---------------- scratch (static device globals; no runtime allocation) ----
__device__ float g_Y[(size_t)BATCH * HH];      // 64 MB (Yq then Yk)
__device__ float g_Qp[8 * BATCH * HDIM];
__device__ float g_Q[BATCH * HDIM];
__device__ float g_w[BATCH * HDIM];
__device__ float g_compat[BATCH * NSEQ];
__device__ int   g_idx[BATCH * NFOCUS];

// ======================= mma.sync helpers (HMMA path) =======================
__device__ __forceinline__ uint32_t smem_u32(const void* p) {
    uint32_t a;
    asm("{ .reg .u64 t; cvta.to.shared.u64 t, %1; cvt.u32.u64 %0, t; }"
        : "=r"(a) : "l"(p));
    return a;
}
__device__ __forceinline__ void ldsm4(uint32_t* r, uint32_t a) {
    asm volatile("ldmatrix.sync.aligned.m8n8.x4.shared.b16 {%0,%1,%2,%3}, [%4];"
                 : "=r"(r[0]), "=r"(r[1]), "=r"(r[2]), "=r"(r[3]) : "r"(a));
}
__device__ __forceinline__ void ldsm2(uint32_t* r, uint32_t a) {
    asm volatile("ldmatrix.sync.aligned.m8n8.x2.shared.b16 {%0,%1}, [%2];"
                 : "=r"(r[0]), "=r"(r[1]) : "r"(a));
}
__device__ __forceinline__ void mma16816(float* c, const uint32_t* a, const uint32_t* b) {
    asm volatile(
        "mma.sync.aligned.m16n8k16.row.col.f32.f16.f16.f32 "
        "{%0,%1,%2,%3}, {%4,%5,%6,%7}, {%8,%9}, {%0,%1,%2,%3};"
        : "+f"(c[0]), "+f"(c[1]), "+f"(c[2]), "+f"(c[3])
        : "r"(a[0]), "r"(a[1]), "r"(a[2]), "r"(a[3]), "r"(b[0]), "r"(b[1]));
}
// Split a PAIR of fp32 into two packed fp16 levels with only 2 cvt instrs.
__device__ __forceinline__ void split_pair(float x0, float x1,
                                           uint32_t& uA, uint32_t& uB) {
    uint32_t b0 = __float_as_uint(x0), b1 = __float_as_uint(x1);
    float t0 = __uint_as_float((b0 + 0xFFFu + ((b0 >> 13) & 1u)) & 0xFFFFE000u);
    float t1 = __uint_as_float((b1 + 0xFFFu + ((b1 >> 13) & 1u)) & 0xFFFFE000u);
    float r0 = (x0 - t0) * 2048.0f;
    float r1 = (x1 - t1) * 2048.0f;
    asm("cvt.rn.f16x2.f32 %0, %1, %2;" : "=r"(uA) : "f"(t1), "f"(t0));
    asm("cvt.rn.f16x2.f32 %0, %1, %2;" : "=r"(uB) : "f"(r1), "f"(r0));
}
__device__ __forceinline__ void cp16(uint32_t dst, const void* src) {
    asm volatile("cp.async.cg.shared.global [%0], [%1], 16;"
                 :: "r"(dst), "l"(src) : "memory");
}
#define CP_COMMIT() asm volatile("cp.async.commit_group;" ::: "memory")

// ========= emulated-fp32 GEMM via 2-way fp16 split (3 HMMA products) ========
// NTILE 256, 16 warps x (32m x 32n). 3-stage raw cp.async ring (issue placed
// after the iteration barrier -> ring overwrite is barrier-separated from its
// reader), double-buffered fp16 stage.
#define KC 32                        // k per chunk
#define NCHUNK (HDIM / KC)           // 16
#define NTILE 256                    // n per CTA
#define THREADS 512
#define ROWB 80                      // padded fp16 smem row bytes (64B + 16 pad)
// smem byte offsets:
#define RAWW_OFF(st)      ((st) * 32768u)                     // 32k x 256n fp32
#define RAWX_OFF(st)      (98304u + (st) * 8192u)             // 64b x 32k fp32
#define WS_OFF(buf, lvl)  (122880u + (buf) * 51200u + (lvl) * 20480u)
#define XS_OFF(buf, lvl)  (122880u + (buf) * 51200u + 40960u + (lvl) * 5120u)
#define SMEM_BYTES 225280

__global__ __launch_bounds__(THREADS, 1) void gemm_mma(
    const float* __restrict__ X, const float* __restrict__ W,
    const float* __restrict__ bias)
{
    extern __shared__ __align__(16) char smem_raw[];
    const uint32_t sb = smem_u32(smem_raw);
    const int tid = threadIdx.x;
    const int wid = tid >> 5, lane = tid & 31;
    const int n0 = blockIdx.x * NTILE;

    // warp tile: 32 batches (mpair) x 32 n (noct 0..7)
    const int mpair = wid & 1;
    const int noct  = wid >> 1;

    float lo[2][4][4], hi[2][4][4];
    #pragma unroll
    for (int m = 0; m < 2; m++)
        #pragma unroll
        for (int j = 0; j < 4; j++)
            #pragma unroll
            for (int q = 0; q < 4; q++) { lo[m][j][q] = 0.f; hi[m][j][q] = 0.f; }

    // converter mappings
    const int wn = tid & 255, wkh = tid >> 8;     // W: n col, k-half (16k each)
    const int xb = tid >> 3, xq = tid & 7;        // X: batch row, k-quad

    // fragment smem base offsets
    const uint32_t a_row = (uint32_t)(32 * mpair + (lane & 15)) * ROWB + ((lane >> 4) << 4);
    const uint32_t b_row = (uint32_t)(noct * 32 + (lane & 7)) * ROWB + (((lane >> 3) & 1) << 4);

    #define ISSUE_STAGE(stg, chunk) do {                                         \
        const uint32_t wdst = sb + RAWW_OFF(stg);                                \
        const float* wsrc = W + (size_t)((chunk) * KC) * HH + n0;                \
        _Pragma("unroll")                                                        \
        for (int i = 0; i < 4; i++) {                                            \
            const int r = (tid >> 6) + i * 8;                                    \
            const int sg = tid & 63;                                             \
            cp16(wdst + (uint32_t)r * 1024u + (uint32_t)sg * 16u,                \
                 wsrc + (size_t)r * HH + sg * 4);                                \
        }                                                                        \
        cp16(sb + RAWX_OFF(stg) + (uint32_t)xb * 128u + (uint32_t)xq * 16u,      \
             X + (size_t)xb * HDIM + (chunk) * KC + xq * 4);                     \
        CP_COMMIT();                                                             \
    } while (0)

    #define CONVERT_STAGE(stg, buf) do {                                         \
        const char* rw = smem_raw + RAWW_OFF(stg);                               \
        float wv[16];                                                            \
        _Pragma("unroll")                                                        \
        for (int j = 0; j < 16; j++)                                             \
            wv[j] = *(const float*)(rw + (uint32_t)(wkh * 16 + j) * 1024u + (uint32_t)wn * 4u); \
        uint32_t u1[8], u2[8];                                                   \
        _Pragma("unroll")                                                        \
        for (int p = 0; p < 8; p++)                                              \
            split_pair(wv[2 * p], wv[2 * p + 1], u1[p], u2[p]);                  \
        const uint32_t rb = (uint32_t)wn * ROWB + wkh * 32;                      \
        asm volatile("st.shared.v4.b32 [%0], {%1,%2,%3,%4};" ::                  \
            "r"(sb + WS_OFF(buf, 0) + rb), "r"(u1[0]), "r"(u1[1]), "r"(u1[2]), "r"(u1[3]) : "memory"); \
        asm volatile("st.shared.v4.b32 [%0], {%1,%2,%3,%4};" ::                  \
            "r"(sb + WS_OFF(buf, 0) + rb + 16), "r"(u1[4]), "r"(u1[5]), "r"(u1[6]), "r"(u1[7]) : "memory"); \
        asm volatile("st.shared.v4.b32 [%0], {%1,%2,%3,%4};" ::                  \
            "r"(sb + WS_OFF(buf, 1) + rb), "r"(u2[0]), "r"(u2[1]), "r"(u2[2]), "r"(u2[3]) : "memory"); \
        asm volatile("st.shared.v4.b32 [%0], {%1,%2,%3,%4};" ::                  \
            "r"(sb + WS_OFF(buf, 1) + rb + 16), "r"(u2[4]), "r"(u2[5]), "r"(u2[6]), "r"(u2[7]) : "memory"); \
        float4 xv = *(const float4*)(smem_raw + RAWX_OFF(stg) + (uint32_t)xb * 128u + (uint32_t)xq * 16u); \
        uint32_t v1[2], v2[2];                                                   \
        split_pair(xv.x, xv.y, v1[0], v2[0]);                                    \
        split_pair(xv.z, xv.w, v1[1], v2[1]);                                    \
        const uint32_t xrb = (uint32_t)xb * ROWB + xq * 8;                       \
        asm volatile("st.shared.v2.b32 [%0], {%1,%2};" ::                        \
            "r"(sb + XS_OFF(buf, 0) + xrb), "r"(v1[0]), "r"(v1[1]) : "memory");  \
        asm volatile("st.shared.v2.b32 [%0], {%1,%2};" ::                        \
            "r"(sb + XS_OFF(buf, 1) + xrb), "r"(v2[0]), "r"(v2[1]) : "memory");  \
    } while (0)

    // ---- prologue: stages 0..2 in flight; convert chunk 0 ----
    ISSUE_STAGE(0, 0);
    ISSUE_STAGE(1, 1);
    ISSUE_STAGE(2, 2);
    asm volatile("cp.async.wait_group 2;" ::: "memory");
    __syncthreads();
    CONVERT_STAGE(0, 0);

    for (int kc = 0; kc < NCHUNK; kc++) {
        // wait for raw chunk kc+1 (at most one newer group outstanding)
        if (kc + 1 < NCHUNK) {
            if (kc <= NCHUNK - 3) asm volatile("cp.async.wait_group 1;" ::: "memory");
            else                  asm volatile("cp.async.wait_group 0;" ::: "memory");
        }
        __syncthreads();

        // issue AFTER the barrier: stage kc%3's reader (convert kc, last iter)
        // is barrier-separated from this overwrite.
        if (kc + 3 < NCHUNK) ISSUE_STAGE((kc + 3) % 3, kc + 3);

        if (kc + 1 < NCHUNK) CONVERT_STAGE((kc + 1) % 3, (kc + 1) & 1);

        // ---- mma on current fp16 buffer ----
        const int cur = kc & 1;
        #pragma unroll
        for (int ks = 0; ks < 2; ks++) {
            uint32_t a1[2][4], a2[2][4];
            #pragma unroll
            for (int m = 0; m < 2; m++) {
                ldsm4(a1[m], sb + XS_OFF(cur, 0) + a_row + (uint32_t)m * (16 * ROWB) + ks * 32);
                ldsm4(a2[m], sb + XS_OFF(cur, 1) + a_row + (uint32_t)m * (16 * ROWB) + ks * 32);
            }
            #pragma unroll
            for (int j = 0; j < 4; j++) {
                uint32_t b1[2], b2[2];
                ldsm2(b1, sb + WS_OFF(cur, 0) + b_row + (uint32_t)j * (8 * ROWB) + ks * 32);
                ldsm2(b2, sb + WS_OFF(cur, 1) + b_row + (uint32_t)j * (8 * ROWB) + ks * 32);
                #pragma unroll
                for (int m = 0; m < 2; m++) {
                    mma16816(lo[m][j], a1[m], b1);
                    mma16816(hi[m][j], a1[m], b2);
                    mma16816(hi[m][j], a2[m], b1);
                }
            }
        }
    }

    // ---- epilogue: Y = lo + hi/2048 + bias ----
    const float s = 1.0f / 2048.0f;
    const int ncol = n0 + noct * 32 + (lane & 3) * 2;
    #pragma unroll
    for (int m = 0; m < 2; m++) {
        const int brow = 32 * mpair + 16 * m + (lane >> 2);
        #pragma unroll
        for (int j = 0; j < 4; j++) {
            const int n = ncol + j * 8;
            const float2 bz = *(const float2*)&bias[n];
            float2 o0 = make_float2(fmaf(hi[m][j][0], s, lo[m][j][0]) + bz.x,
                                    fmaf(hi[m][j][1], s, lo[m][j][1]) + bz.y);
            float2 o1 = make_float2(fmaf(hi[m][j][2], s, lo[m][j][2]) + bz.x,
                                    fmaf(hi[m][j][3], s, lo[m][j][3]) + bz.y);
            *(float2*)&g_Y[(size_t)brow * HH + n]       = o0;
            *(float2*)&g_Y[(size_t)(brow + 8) * HH + n] = o1;
        }
    }
    #undef ISSUE_STAGE
    #undef CONVERT_STAGE
}

// ---------------- Qpart[s,b,k] = sum_{h in slice s} x[b,h] * Y[b, h*H + k] --
__global__ void contract_q(const float* __restrict__ X) {
    const int b = blockIdx.y, s = blockIdx.x;
    const int k = threadIdx.x;  // 512
    __shared__ float xs[64];
    if (k < 64) xs[k] = X[b * HDIM + s * 64 + k];
    __syncthreads();
    const float* Yb = g_Y + (size_t)b * HH + (size_t)s * 64 * HDIM + k;
    float a0 = 0.f, a1 = 0.f, a2 = 0.f, a3 = 0.f;
    #pragma unroll
    for (int hh = 0; hh < 64; hh += 4) {
        a0 = fmaf(xs[hh + 0], Yb[(hh + 0) * HDIM], a0);
        a1 = fmaf(xs[hh + 1], Yb[(hh + 1) * HDIM], a1);
        a2 = fmaf(xs[hh + 2], Yb[(hh + 2) * HDIM], a2);
        a3 = fmaf(xs[hh + 3], Yb[(hh + 3) * HDIM], a3);
    }
    g_Qp[(s * BATCH + b) * HDIM + k] = (a0 + a1) + (a2 + a3);
}

__global__ void reduce_q() {
    const int b = blockIdx.x, k = threadIdx.x;
    float v = 0.f;
    #pragma unroll
    for (int s = 0; s < 8; s++) v += g_Qp[(s * BATCH + b) * HDIM + k];
    g_Q[b * HDIM + k] = v;
}

// ---------------- w[b,h] = < Y[b, h*H : h*H+H] , Q[b,:] > -------------------
__global__ void contract_w() {
    const int b = blockIdx.y;
    const int warp = threadIdx.x >> 5, lane = threadIdx.x & 31;
    const int h = blockIdx.x * 8 + warp;
    __shared__ float qs[HDIM];
    for (int i = threadIdx.x; i < HDIM; i += 256) qs[i] = g_Q[b * HDIM + i];
    __syncthreads();
    const float* Yb = g_Y + (size_t)b * HH + (size_t)h * HDIM;
    float acc = 0.f;
    #pragma unroll
    for (int s2 = 0; s2 < 4; s2++) {
        const int i4 = lane + s2 * 32;
        float4 y = *(const float4*)&Yb[i4 * 4];
        float4 q = *(const float4*)&qs[i4 * 4];
        acc += y.x * q.x + y.y * q.y + y.z * q.z + y.w * q.w;
    }
    #pragma unroll
    for (int off = 16; off; off >>= 1) acc += __shfl_xor_sync(~0u, acc, off);
    if (lane == 0) g_w[b * HDIM + h] = acc;
}

// ---------------- compat[b,n] = norm * < ve[b,n,:], w[b,:] > ----------------
__global__ void compat_k(const float* __restrict__ ve) {
    const int b = blockIdx.y;
    const int warp = threadIdx.x >> 5, lane = threadIdx.x & 31;
    const int n = blockIdx.x * 8 + warp;
    __shared__ float ws[HDIM];
    for (int i = threadIdx.x; i < HDIM; i += 256) ws[i] = g_w[b * HDIM + i];
    __syncthreads();
    const float* v = ve + ((size_t)b * NSEQ + n) * HDIM;
    float acc = 0.f;
    #pragma unroll
    for (int s2 = 0; s2 < 4; s2++) {
        const int i4 = lane + s2 * 32;
        float4 y = *(const float4*)&v[i4 * 4];
        float4 q = *(const float4*)&ws[i4 * 4];
        acc += y.x * q.x + y.y * q.y + y.z * q.z + y.w * q.w;
    }
    #pragma unroll
    for (int off = 16; off; off >>= 1) acc += __shfl_xor_sync(~0u, acc, off);
    if (lane == 0) g_compat[b * NSEQ + n] = acc * 0.04419417382415922f;
}

// ---------------- per-batch ranking with fp32-exp flush boundary ------------
__global__ __launch_bounds__(1024) void topk_k() {
    __shared__ unsigned sk[NSEQ];
    __shared__ int      si[NSEQ];
    __shared__ float    redf[32];
    const int b = blockIdx.x, t = threadIdx.x;
    const int lane = t & 31, warp = t >> 5;

    const float c0 = g_compat[b * NSEQ + t];
    const float c1 = g_compat[b * NSEQ + t + 1024];

    float m = fmaxf(c0, c1);
    #pragma unroll
    for (int o = 16; o; o >>= 1) m = fmaxf(m, __shfl_xor_sync(~0u, m, o));
    if (lane == 0) redf[warp] = m;
    __syncthreads();
    float mx = redf[0];
    #pragma unroll
    for (int i = 1; i < 32; i++) mx = fmaxf(mx, redf[i]);

    auto mkkey = [&](float c) -> unsigned {
        float d = c - mx;
        if (d < -87.33654785f) return 0u;
        unsigned u = __float_as_uint(c);
        return (u & 0x80000000u) ? ~u : (u | 0x80000000u);
    };
    sk[t]        = mkkey(c0);  si[t]        = t;
    sk[t + 1024] = mkkey(c1);  si[t + 1024] = t + 1024;

    for (int k = 2; k <= NSEQ; k <<= 1) {
        for (int j = k >> 1; j > 0; j >>= 1) {
            __syncthreads();
            #pragma unroll
            for (int half = 0; half < 2; half++) {
                const int i = half * 1024 + t;
                const int ixj = i ^ j;
                if (ixj > i) {
                    const bool desc = ((i & k) == 0);
                    unsigned ki = sk[i], kj = sk[ixj];
                    int      ii = si[i], ij = si[ixj];
                    const bool jBeforeI = (kj > ki) || (kj == ki && ij < ii);
                    if (desc ? jBeforeI : !jBeforeI) {
                        sk[i] = kj; sk[ixj] = ki;
                        si[i] = ij; si[ixj] = ii;
                    }
                }
            }
        }
    }
    __syncthreads();
    if (t < NFOCUS) g_idx[b * NFOCUS + t] = si[t];
}

// ---------------- gather: out[b,r,:] = ve[b, idx[b,r], :] -------------------
__global__ void gather_k(const float* __restrict__ ve, float* __restrict__ out) {
    const int b = blockIdx.y, r = blockIdx.x;
    const int idx = g_idx[b * NFOCUS + r];
    const float4* src = (const float4*)(ve + ((size_t)b * NSEQ + idx) * HDIM);
    float4* dst = (float4*)(out + ((size_t)b * NFOCUS + r) * HDIM);
    dst[threadIdx.x] = src[threadIdx.x];
}

// ---------------- launch ----------------------------------------------------
extern "C" void kernel_launch(void* const* d_in, const int* in_sizes, int n_in,
                              void* d_out, int out_size) {
    const float* vs = (const float*)d_in[0];   // (64, 1, 512)
    const float* ve = (const float*)d_in[1];   // (64, 2048, 512)
    const float* Wq = (const float*)d_in[2];   // (512, 262144)
    const float* bq = (const float*)d_in[3];   // (262144,)
    const float* Wk = (const float*)d_in[4];   // (512, 262144)
    const float* bk = (const float*)d_in[5];   // (262144,)
    float* out = (float*)d_out;                // (64, 256, 512)

    cudaFuncSetAttribute(gemm_mma, cudaFuncAttributeMaxDynamicSharedMemorySize, SMEM_BYTES);

    gemm_mma<<<HH / NTILE, THREADS, SMEM_BYTES>>>(vs, Wq, bq);
    contract_q<<<dim3(8, BATCH), 512>>>(vs);
    reduce_q<<<BATCH, HDIM>>>();

    gemm_mma<<<HH / NTILE, THREADS, SMEM_BYTES>>>(vs, Wk, bk);
    contract_w<<<dim3(64, BATCH), 256>>>();

    compat_k<<<dim3(NSEQ / 8, BATCH), 256>>>(ve);
    topk_k<<<BATCH, 1024>>>();
    gather_k<<<dim3(NFOCUS, BATCH), 128>>>(ve, out);
}

// round 14
// speedup vs baseline: 1.5368x; 1.0739x over previous
#include <cuda_runtime.h>
#include <cuda_fp16.h>
#include <cstdint>

#define BATCH 64
#define HDIM 512
#define HH 262144      // HDIM*HDIM
#define NSEQ 2048
#define NFOCUS 256

// ---------------- scratch (static device globals; no runtime allocation) ----
__device__ float g_Y[(size_t)BATCH * HH];      // 64 MB (Yq then Yk)
__device__ float g_Qp[8 * BATCH * HDIM];
__device__ float g_Q[BATCH * HDIM];
__device__ float g_w[BATCH * HDIM];
__device__ float g_compat[BATCH * NSEQ];
__device__ int   g_idx[BATCH * NFOCUS];

// ======================= mma.sync helpers (HMMA path) =======================
__device__ __forceinline__ uint32_t smem_u32(const void* p) {
    uint32_t a;
    asm("{ .reg .u64 t; cvta.to.shared.u64 t, %1; cvt.u32.u64 %0, t; }"
        : "=r"(a) : "l"(p));
    return a;
}
__device__ __forceinline__ void ldsm4(uint32_t* r, uint32_t a) {
    asm volatile("ldmatrix.sync.aligned.m8n8.x4.shared.b16 {%0,%1,%2,%3}, [%4];"
                 : "=r"(r[0]), "=r"(r[1]), "=r"(r[2]), "=r"(r[3]) : "r"(a));
}
__device__ __forceinline__ void ldsm2(uint32_t* r, uint32_t a) {
    asm volatile("ldmatrix.sync.aligned.m8n8.x2.shared.b16 {%0,%1}, [%2];"
                 : "=r"(r[0]), "=r"(r[1]) : "r"(a));
}
__device__ __forceinline__ void mma16816(float* c, const uint32_t* a, const uint32_t* b) {
    asm volatile(
        "mma.sync.aligned.m16n8k16.row.col.f32.f16.f16.f32 "
        "{%0,%1,%2,%3}, {%4,%5,%6,%7}, {%8,%9}, {%0,%1,%2,%3};"
        : "+f"(c[0]), "+f"(c[1]), "+f"(c[2]), "+f"(c[3])
        : "r"(a[0]), "r"(a[1]), "r"(a[2]), "r"(a[3]), "r"(b[0]), "r"(b[1]));
}
// Split a PAIR of fp32 into two packed fp16 levels with only 2 cvt instrs.
__device__ __forceinline__ void split_pair(float x0, float x1,
                                           uint32_t& uA, uint32_t& uB) {
    uint32_t b0 = __float_as_uint(x0), b1 = __float_as_uint(x1);
    float t0 = __uint_as_float((b0 + 0xFFFu + ((b0 >> 13) & 1u)) & 0xFFFFE000u);
    float t1 = __uint_as_float((b1 + 0xFFFu + ((b1 >> 13) & 1u)) & 0xFFFFE000u);
    float r0 = (x0 - t0) * 2048.0f;
    float r1 = (x1 - t1) * 2048.0f;
    asm("cvt.rn.f16x2.f32 %0, %1, %2;" : "=r"(uA) : "f"(t1), "f"(t0));
    asm("cvt.rn.f16x2.f32 %0, %1, %2;" : "=r"(uB) : "f"(r1), "f"(r0));
}
__device__ __forceinline__ void cp16(uint32_t dst, const void* src) {
    asm volatile("cp.async.cg.shared.global [%0], [%1], 16;"
                 :: "r"(dst), "l"(src) : "memory");
}
#define CP_COMMIT() asm volatile("cp.async.commit_group;" ::: "memory")

// ========= emulated-fp32 GEMM via 2-way fp16 split (3 HMMA products) ========
// 2 CTAs/SM. Round-12-proven ordering: wait_group -> __syncthreads -> issue ->
// convert -> mma. 3-stage W raw ring; X prefetched into register double-buffer
// (no X raw ring) to fit 2 CTAs in smem.
#define KC 32                        // k per chunk
#define NCHUNK (HDIM / KC)           // 16
#define NTILE 128                    // n per CTA
#define THREADS 256
#define ROWB 80                      // padded fp16 smem row bytes (64B + 16 pad)
// smem byte offsets:
#define RAWW_OFF(st)      ((st) * 16384u)                     // 32k x 128n fp32, 3 stages
#define WS_OFF(buf, lvl)  (49152u + (buf) * 30720u + (lvl) * 10240u)
#define XS_OFF(buf, lvl)  (49152u + (buf) * 30720u + 20480u + (lvl) * 5120u)
#define SMEM_BYTES 110592

__global__ __launch_bounds__(THREADS, 2) void gemm_mma(
    const float* __restrict__ X, const float* __restrict__ W,
    const float* __restrict__ bias)
{
    extern __shared__ __align__(16) char smem_raw[];
    const uint32_t sb = smem_u32(smem_raw);
    const int tid = threadIdx.x;
    const int wid = tid >> 5, lane = tid & 31;
    const int n0 = blockIdx.x * NTILE;

    // warp tile: 32 batches (mpair) x 32 n (noct 0..3)
    const int mpair = wid & 1;
    const int noct  = wid >> 1;

    float lo[2][4][4], hi[2][4][4];
    #pragma unroll
    for (int m = 0; m < 2; m++)
        #pragma unroll
        for (int j = 0; j < 4; j++)
            #pragma unroll
            for (int q = 0; q < 4; q++) { lo[m][j][q] = 0.f; hi[m][j][q] = 0.f; }

    // converter mappings (256 threads)
    const int wn = tid & 127, wkh = tid >> 7;     // W: n col, k-half (16k each)
    const int xb = tid >> 2, xq = tid & 3;        // X: batch row, k-octet(8)

    // X register double-buffer (one chunk: 2 float4 per thread)
    float4 xr0, xr1;

    // fragment smem base offsets
    const uint32_t a_row = (uint32_t)(32 * mpair + (lane & 15)) * ROWB + ((lane >> 4) << 4);
    const uint32_t b_row = (uint32_t)(noct * 32 + (lane & 7)) * ROWB + (((lane >> 3) & 1) << 4);

    #define ISSUE_STAGE(stg, chunk) do {                                         \
        const uint32_t wdst = sb + RAWW_OFF(stg);                                \
        const float* wsrc = W + (size_t)((chunk) * KC) * HH + n0;                \
        _Pragma("unroll")                                                        \
        for (int i = 0; i < 4; i++) {                                            \
            const int s2 = tid + i * 256;                                        \
            const int r = s2 >> 5, sg = s2 & 31;                                 \
            cp16(wdst + (uint32_t)r * 512u + (uint32_t)sg * 16u,                 \
                 wsrc + (size_t)r * HH + sg * 4);                                \
        }                                                                        \
        CP_COMMIT();                                                             \
    } while (0)

    #define XLOAD(chunk) do {                                                    \
        const float* xsrc = X + (size_t)xb * HDIM + (chunk) * KC + xq * 8;       \
        xr0 = __ldg((const float4*)xsrc);                                        \
        xr1 = __ldg((const float4*)(xsrc + 4));                                  \
    } while (0)

    #define CONVERT_STAGE(stg, buf) do {                                         \
        const char* rw = smem_raw + RAWW_OFF(stg);                               \
        float wv[16];                                                            \
        _Pragma("unroll")                                                        \
        for (int j = 0; j < 16; j++)                                             \
            wv[j] = *(const float*)(rw + (uint32_t)(wkh * 16 + j) * 512u + (uint32_t)wn * 4u); \
        uint32_t u1[8], u2[8];                                                   \
        _Pragma("unroll")                                                        \
        for (int p = 0; p < 8; p++)                                              \
            split_pair(wv[2 * p], wv[2 * p + 1], u1[p], u2[p]);                  \
        const uint32_t rb = (uint32_t)wn * ROWB + wkh * 32;                      \
        asm volatile("st.shared.v4.b32 [%0], {%1,%2,%3,%4};" ::                  \
            "r"(sb + WS_OFF(buf, 0) + rb), "r"(u1[0]), "r"(u1[1]), "r"(u1[2]), "r"(u1[3]) : "memory"); \
        asm volatile("st.shared.v4.b32 [%0], {%1,%2,%3,%4};" ::                  \
            "r"(sb + WS_OFF(buf, 0) + rb + 16), "r"(u1[4]), "r"(u1[5]), "r"(u1[6]), "r"(u1[7]) : "memory"); \
        asm volatile("st.shared.v4.b32 [%0], {%1,%2,%3,%4};" ::                  \
            "r"(sb + WS_OFF(buf, 1) + rb), "r"(u2[0]), "r"(u2[1]), "r"(u2[2]), "r"(u2[3]) : "memory"); \
        asm volatile("st.shared.v4.b32 [%0], {%1,%2,%3,%4};" ::                  \
            "r"(sb + WS_OFF(buf, 1) + rb + 16), "r"(u2[4]), "r"(u2[5]), "r"(u2[6]), "r"(u2[7]) : "memory"); \
        uint32_t v1[4], v2[4];                                                   \
        split_pair(xr0.x, xr0.y, v1[0], v2[0]);                                  \
        split_pair(xr0.z, xr0.w, v1[1], v2[1]);                                  \
        split_pair(xr1.x, xr1.y, v1[2], v2[2]);                                  \
        split_pair(xr1.z, xr1.w, v1[3], v2[3]);                                  \
        const uint32_t xrb = (uint32_t)xb * ROWB + xq * 16;                      \
        asm volatile("st.shared.v4.b32 [%0], {%1,%2,%3,%4};" ::                  \
            "r"(sb + XS_OFF(buf, 0) + xrb), "r"(v1[0]), "r"(v1[1]), "r"(v1[2]), "r"(v1[3]) : "memory"); \
        asm volatile("st.shared.v4.b32 [%0], {%1,%2,%3,%4};" ::                  \
            "r"(sb + XS_OFF(buf, 1) + xrb), "r"(v2[0]), "r"(v2[1]), "r"(v2[2]), "r"(v2[3]) : "memory"); \
    } while (0)

    // ---- prologue: 3 W stages in flight; convert chunk 0 ----
    ISSUE_STAGE(0, 0);
    ISSUE_STAGE(1, 1);
    ISSUE_STAGE(2, 2);
    XLOAD(0);
    asm volatile("cp.async.wait_group 2;" ::: "memory");   // own G0 complete
    __syncthreads();                                       // cross-thread visible
    CONVERT_STAGE(0, 0);
    XLOAD(1);                                              // X for next convert

    for (int kc = 0; kc < NCHUNK; kc++) {
        // complete raw chunk kc+1 (own groups), then barrier for visibility
        if (kc + 1 < NCHUNK) {
            if (kc <= NCHUNK - 3) asm volatile("cp.async.wait_group 1;" ::: "memory");
            else                  asm volatile("cp.async.wait_group 0;" ::: "memory");
        }
        __syncthreads();

        // overwrite raw stage kc%3 (its reader, convert(kc), ran pre-barrier)
        if (kc + 3 < NCHUNK) ISSUE_STAGE(kc % 3, kc + 3);

        if (kc + 1 < NCHUNK) {
            CONVERT_STAGE((kc + 1) % 3, (kc + 1) & 1);
            if (kc + 2 < NCHUNK) XLOAD(kc + 2);
        }

        // ---- mma on fp16 buf kc&1 ----
        const int cur = kc & 1;
        #pragma unroll
        for (int ks = 0; ks < 2; ks++) {
            uint32_t a1[2][4], a2[2][4];
            #pragma unroll
            for (int m = 0; m < 2; m++) {
                ldsm4(a1[m], sb + XS_OFF(cur, 0) + a_row + (uint32_t)m * (16 * ROWB) + ks * 32);
                ldsm4(a2[m], sb + XS_OFF(cur, 1) + a_row + (uint32_t)m * (16 * ROWB) + ks * 32);
            }
            #pragma unroll
            for (int j = 0; j < 4; j++) {
                uint32_t b1[2], b2[2];
                ldsm2(b1, sb + WS_OFF(cur, 0) + b_row + (uint32_t)j * (8 * ROWB) + ks * 32);
                ldsm2(b2, sb + WS_OFF(cur, 1) + b_row + (uint32_t)j * (8 * ROWB) + ks * 32);
                #pragma unroll
                for (int m = 0; m < 2; m++) {
                    mma16816(lo[m][j], a1[m], b1);
                    mma16816(hi[m][j], a1[m], b2);
                    mma16816(hi[m][j], a2[m], b1);
                }
            }
        }
    }

    // ---- epilogue: Y = lo + hi/2048 + bias ----
    const float s = 1.0f / 2048.0f;
    const int ncol = n0 + noct * 32 + (lane & 3) * 2;
    #pragma unroll
    for (int m = 0; m < 2; m++) {
        const int brow = 32 * mpair + 16 * m + (lane >> 2);
        #pragma unroll
        for (int j = 0; j < 4; j++) {
            const int n = ncol + j * 8;
            const float2 bz = *(const float2*)&bias[n];
            float2 o0 = make_float2(fmaf(hi[m][j][0], s, lo[m][j][0]) + bz.x,
                                    fmaf(hi[m][j][1], s, lo[m][j][1]) + bz.y);
            float2 o1 = make_float2(fmaf(hi[m][j][2], s, lo[m][j][2]) + bz.x,
                                    fmaf(hi[m][j][3], s, lo[m][j][3]) + bz.y);
            *(float2*)&g_Y[(size_t)brow * HH + n]       = o0;
            *(float2*)&g_Y[(size_t)(brow + 8) * HH + n] = o1;
        }
    }
    #undef ISSUE_STAGE
    #undef XLOAD
    #undef CONVERT_STAGE
}

// ---------------- Qpart[s,b,k] = sum_{h in slice s} x[b,h] * Y[b, h*H + k] --
__global__ void contract_q(const float* __restrict__ X) {
    const int b = blockIdx.y, s = blockIdx.x;
    const int k = threadIdx.x;  // 512
    __shared__ float xs[64];
    if (k < 64) xs[k] = X[b * HDIM + s * 64 + k];
    __syncthreads();
    const float* Yb = g_Y + (size_t)b * HH + (size_t)s * 64 * HDIM + k;
    float a0 = 0.f, a1 = 0.f, a2 = 0.f, a3 = 0.f;
    #pragma unroll
    for (int hh = 0; hh < 64; hh += 4) {
        a0 = fmaf(xs[hh + 0], Yb[(hh + 0) * HDIM], a0);
        a1 = fmaf(xs[hh + 1], Yb[(hh + 1) * HDIM], a1);
        a2 = fmaf(xs[hh + 2], Yb[(hh + 2) * HDIM], a2);
        a3 = fmaf(xs[hh + 3], Yb[(hh + 3) * HDIM], a3);
    }
    g_Qp[(s * BATCH + b) * HDIM + k] = (a0 + a1) + (a2 + a3);
}

__global__ void reduce_q() {
    const int b = blockIdx.x, k = threadIdx.x;
    float v = 0.f;
    #pragma unroll
    for (int s = 0; s < 8; s++) v += g_Qp[(s * BATCH + b) * HDIM + k];
    g_Q[b * HDIM + k] = v;
}

// ---------------- w[b,h] = < Y[b, h*H : h*H+H] , Q[b,:] > -------------------
__global__ void contract_w() {
    const int b = blockIdx.y;
    const int warp = threadIdx.x >> 5, lane = threadIdx.x & 31;
    const int h = blockIdx.x * 8 + warp;
    __shared__ float qs[HDIM];
    for (int i = threadIdx.x; i < HDIM; i += 256) qs[i] = g_Q[b * HDIM + i];
    __syncthreads();
    const float* Yb = g_Y + (size_t)b * HH + (size_t)h * HDIM;
    float acc = 0.f;
    #pragma unroll
    for (int s2 = 0; s2 < 4; s2++) {
        const int i4 = lane + s2 * 32;
        float4 y = *(const float4*)&Yb[i4 * 4];
        float4 q = *(const float4*)&qs[i4 * 4];
        acc += y.x * q.x + y.y * q.y + y.z * q.z + y.w * q.w;
    }
    #pragma unroll
    for (int off = 16; off; off >>= 1) acc += __shfl_xor_sync(~0u, acc, off);
    if (lane == 0) g_w[b * HDIM + h] = acc;
}

// ---------------- compat[b,n] = norm * < ve[b,n,:], w[b,:] > ----------------
__global__ void compat_k(const float* __restrict__ ve) {
    const int b = blockIdx.y;
    const int warp = threadIdx.x >> 5, lane = threadIdx.x & 31;
    const int n = blockIdx.x * 8 + warp;
    __shared__ float ws[HDIM];
    for (int i = threadIdx.x; i < HDIM; i += 256) ws[i] = g_w[b * HDIM + i];
    __syncthreads();
    const float* v = ve + ((size_t)b * NSEQ + n) * HDIM;
    float acc = 0.f;
    #pragma unroll
    for (int s2 = 0; s2 < 4; s2++) {
        const int i4 = lane + s2 * 32;
        float4 y = *(const float4*)&v[i4 * 4];
        float4 q = *(const float4*)&ws[i4 * 4];
        acc += y.x * q.x + y.y * q.y + y.z * q.z + y.w * q.w;
    }
    #pragma unroll
    for (int off = 16; off; off >>= 1) acc += __shfl_xor_sync(~0u, acc, off);
    if (lane == 0) g_compat[b * NSEQ + n] = acc * 0.04419417382415922f;
}

// ---------------- per-batch ranking with fp32-exp flush boundary ------------
__global__ __launch_bounds__(1024) void topk_k() {
    __shared__ unsigned sk[NSEQ];
    __shared__ int      si[NSEQ];
    __shared__ float    redf[32];
    const int b = blockIdx.x, t = threadIdx.x;
    const int lane = t & 31, warp = t >> 5;

    const float c0 = g_compat[b * NSEQ + t];
    const float c1 = g_compat[b * NSEQ + t + 1024];

    float m = fmaxf(c0, c1);
    #pragma unroll
    for (int o = 16; o; o >>= 1) m = fmaxf(m, __shfl_xor_sync(~0u, m, o));
    if (lane == 0) redf[warp] = m;
    __syncthreads();
    float mx = redf[0];
    #pragma unroll
    for (int i = 1; i < 32; i++) mx = fmaxf(mx, redf[i]);

    auto mkkey = [&](float c) -> unsigned {
        float d = c - mx;
        if (d < -87.33654785f) return 0u;
        unsigned u = __float_as_uint(c);
        return (u & 0x80000000u) ? ~u : (u | 0x80000000u);
    };
    sk[t]        = mkkey(c0);  si[t]        = t;
    sk[t + 1024] = mkkey(c1);  si[t + 1024] = t + 1024;

    for (int k = 2; k <= NSEQ; k <<= 1) {
        for (int j = k >> 1; j > 0; j >>= 1) {
            __syncthreads();
            #pragma unroll
            for (int half = 0; half < 2; half++) {
                const int i = half * 1024 + t;
                const int ixj = i ^ j;
                if (ixj > i) {
                    const bool desc = ((i & k) == 0);
                    unsigned ki = sk[i], kj = sk[ixj];
                    int      ii = si[i], ij = si[ixj];
                    const bool jBeforeI = (kj > ki) || (kj == ki && ij < ii);
                    if (desc ? jBeforeI : !jBeforeI) {
                        sk[i] = kj; sk[ixj] = ki;
                        si[i] = ij; si[ixj] = ii;
                    }
                }
            }
        }
    }
    __syncthreads();
    if (t < NFOCUS) g_idx[b * NFOCUS + t] = si[t];
}

// ---------------- gather: out[b,r,:] = ve[b, idx[b,r], :] -------------------
__global__ void gather_k(const float* __restrict__ ve, float* __restrict__ out) {
    const int b = blockIdx.y, r = blockIdx.x;
    const int idx = g_idx[b * NFOCUS + r];
    const float4* src = (const float4*)(ve + ((size_t)b * NSEQ + idx) * HDIM);
    float4* dst = (float4*)(out + ((size_t)b * NFOCUS + r) * HDIM);
    dst[threadIdx.x] = src[threadIdx.x];
}

// ---------------- launch ----------------------------------------------------
extern "C" void kernel_launch(void* const* d_in, const int* in_sizes, int n_in,
                              void* d_out, int out_size) {
    const float* vs = (const float*)d_in[0];   // (64, 1, 512)
    const float* ve = (const float*)d_in[1];   // (64, 2048, 512)
    const float* Wq = (const float*)d_in[2];   // (512, 262144)
    const float* bq = (const float*)d_in[3];   // (262144,)
    const float* Wk = (const float*)d_in[4];   // (512, 262144)
    const float* bk = (const float*)d_in[5];   // (262144,)
    float* out = (float*)d_out;                // (64, 256, 512)

    cudaFuncSetAttribute(gemm_mma, cudaFuncAttributeMaxDynamicSharedMemorySize, SMEM_BYTES);

    gemm_mma<<<HH / NTILE, THREADS, SMEM_BYTES>>>(vs, Wq, bq);
    contract_q<<<dim3(8, BATCH), 512>>>(vs);
    reduce_q<<<BATCH, HDIM>>>();

    gemm_mma<<<HH / NTILE, THREADS, SMEM_BYTES>>>(vs, Wk, bk);
    contract_w<<<dim3(64, BATCH), 256>>>();

    compat_k<<<dim3(NSEQ / 8, BATCH), 256>>>(ve);
    topk_k<<<BATCH, 1024>>>();
    gather_k<<<dim3(NFOCUS, BATCH), 128>>>(ve, out);
}

// round 15
// speedup vs baseline: 1.7319x; 1.1269x over previous
#include <cuda_runtime.h>
#include <cuda_fp16.h>
#include <cstdint>

#define BATCH 64
#define HDIM 512
#define HH 262144      // HDIM*HDIM
#define NSEQ 2048
#define NFOCUS 256

// ---------------- scratch (static device globals; no runtime allocation) ----
__device__ float g_Y[(size_t)BATCH * HH];      // 64 MB (Yq then Yk)
__device__ float g_Qp[8 * BATCH * HDIM];
__device__ float g_Q[BATCH * HDIM];
__device__ float g_w[BATCH * HDIM];
__device__ float g_compat[BATCH * NSEQ];
__device__ int   g_idx[BATCH * NFOCUS];

// ======================= mma.sync helpers (HMMA path) =======================
__device__ __forceinline__ uint32_t smem_u32(const void* p) {
    uint32_t a;
    asm("{ .reg .u64 t; cvta.to.shared.u64 t, %1; cvt.u32.u64 %0, t; }"
        : "=r"(a) : "l"(p));
    return a;
}
__device__ __forceinline__ void ldsm4(uint32_t* r, uint32_t a) {
    asm volatile("ldmatrix.sync.aligned.m8n8.x4.shared.b16 {%0,%1,%2,%3}, [%4];"
                 : "=r"(r[0]), "=r"(r[1]), "=r"(r[2]), "=r"(r[3]) : "r"(a));
}
__device__ __forceinline__ void mma16816(float* c, const uint32_t* a, const uint32_t* b) {
    asm volatile(
        "mma.sync.aligned.m16n8k16.row.col.f32.f16.f16.f32 "
        "{%0,%1,%2,%3}, {%4,%5,%6,%7}, {%8,%9}, {%0,%1,%2,%3};"
        : "+f"(c[0]), "+f"(c[1]), "+f"(c[2]), "+f"(c[3])
        : "r"(a[0]), "r"(a[1]), "r"(a[2]), "r"(a[3]), "r"(b[0]), "r"(b[1]));
}
// Split a PAIR of fp32 into two packed fp16 levels with only 2 cvt instrs.
__device__ __forceinline__ void split_pair(float x0, float x1,
                                           uint32_t& uA, uint32_t& uB) {
    uint32_t b0 = __float_as_uint(x0), b1 = __float_as_uint(x1);
    float t0 = __uint_as_float((b0 + 0xFFFu + ((b0 >> 13) & 1u)) & 0xFFFFE000u);
    float t1 = __uint_as_float((b1 + 0xFFFu + ((b1 >> 13) & 1u)) & 0xFFFFE000u);
    float r0 = (x0 - t0) * 2048.0f;
    float r1 = (x1 - t1) * 2048.0f;
    asm("cvt.rn.f16x2.f32 %0, %1, %2;" : "=r"(uA) : "f"(t1), "f"(t0));
    asm("cvt.rn.f16x2.f32 %0, %1, %2;" : "=r"(uB) : "f"(r1), "f"(r0));
}

// ========= emulated-fp32 GEMM via 2-way fp16 split (3 HMMA products) ========
// 2 CTAs/SM. No raw smem ring: W streamed gmem -> regs (1-chunk prefetch,
// single 16-reg buffer) -> split -> fp16 STS. X likewise (8 regs). One
// __syncthreads per chunk. B fragments via ldsm4 (2 j-groups per instr).
#define KC 32                        // k per chunk
#define NCHUNK (HDIM / KC)           // 16
#define NTILE 128                    // n per CTA
#define THREADS 256
#define ROWB 80                      // padded fp16 smem row bytes (64B + 16 pad)
// smem byte offsets (fp16 double-buffer only):
#define WS_OFF(buf, lvl)  ((buf) * 30720u + (lvl) * 10240u)           // 128n x 32k
#define XS_OFF(buf, lvl)  ((buf) * 30720u + 20480u + (lvl) * 5120u)   // 64b x 32k
#define SMEM_BYTES 61440

__global__ __launch_bounds__(THREADS, 2) void gemm_mma(
    const float* __restrict__ X, const float* __restrict__ W,
    const float* __restrict__ bias)
{
    extern __shared__ __align__(16) char smem_raw[];
    const uint32_t sb = smem_u32(smem_raw);
    const int tid = threadIdx.x;
    const int wid = tid >> 5, lane = tid & 31;
    const int n0 = blockIdx.x * NTILE;

    // warp tile: 32 batches (mpair) x 32 n (noct 0..3)
    const int mpair = wid & 1;
    const int noct  = wid >> 1;

    float lo[2][4][4], hi[2][4][4];
    #pragma unroll
    for (int m = 0; m < 2; m++)
        #pragma unroll
        for (int j = 0; j < 4; j++)
            #pragma unroll
            for (int q = 0; q < 4; q++) { lo[m][j][q] = 0.f; hi[m][j][q] = 0.f; }

    // converter mappings (256 threads)
    const int wn = tid & 127, wkh = tid >> 7;     // W: n col, k-half (16k each)
    const int xb = tid >> 2, xq = tid & 3;        // X: batch row, k-octet(8)

    // register prefetch buffers (single-buffer, 1 chunk ahead)
    float  wr[16];
    float4 xr0, xr1;

    // fragment smem base offsets
    const uint32_t a_row  = (uint32_t)(32 * mpair + (lane & 15)) * ROWB + ((lane >> 4) << 4);
    // B ldsm4: lanes 0-7 -> rows n0..n0+7 khalf0; 8-15 khalf1; 16-31 same at +8 rows
    const uint32_t b_row4 = (uint32_t)(noct * 32 + (lane & 7) + ((lane >> 4) << 3)) * ROWB
                          + (((lane >> 3) & 1) << 4);

    #define WLOAD(chunk) do {                                                    \
        const float* wsrc = W + (size_t)((chunk) * KC + wkh * 16) * HH + n0 + wn;\
        _Pragma("unroll")                                                        \
        for (int j = 0; j < 16; j++)                                             \
            wr[j] = __ldcs(wsrc + (size_t)j * HH);                               \
    } while (0)

    #define XLOAD(chunk) do {                                                    \
        const float* xsrc = X + (size_t)xb * HDIM + (chunk) * KC + xq * 8;       \
        xr0 = __ldg((const float4*)xsrc);                                        \
        xr1 = __ldg((const float4*)(xsrc + 4));                                  \
    } while (0)

    #define CONVERT_STAGE(buf) do {                                              \
        uint32_t u1[8], u2[8];                                                   \
        _Pragma("unroll")                                                        \
        for (int p = 0; p < 8; p++)                                              \
            split_pair(wr[2 * p], wr[2 * p + 1], u1[p], u2[p]);                  \
        const uint32_t rb = (uint32_t)wn * ROWB + wkh * 32;                      \
        asm volatile("st.shared.v4.b32 [%0], {%1,%2,%3,%4};" ::                  \
            "r"(sb + WS_OFF(buf, 0) + rb), "r"(u1[0]), "r"(u1[1]), "r"(u1[2]), "r"(u1[3]) : "memory"); \
        asm volatile("st.shared.v4.b32 [%0], {%1,%2,%3,%4};" ::                  \
            "r"(sb + WS_OFF(buf, 0) + rb + 16), "r"(u1[4]), "r"(u1[5]), "r"(u1[6]), "r"(u1[7]) : "memory"); \
        asm volatile("st.shared.v4.b32 [%0], {%1,%2,%3,%4};" ::                  \
            "r"(sb + WS_OFF(buf, 1) + rb), "r"(u2[0]), "r"(u2[1]), "r"(u2[2]), "r"(u2[3]) : "memory"); \
        asm volatile("st.shared.v4.b32 [%0], {%1,%2,%3,%4};" ::                  \
            "r"(sb + WS_OFF(buf, 1) + rb + 16), "r"(u2[4]), "r"(u2[5]), "r"(u2[6]), "r"(u2[7]) : "memory"); \
        uint32_t v1[4], v2[4];                                                   \
        split_pair(xr0.x, xr0.y, v1[0], v2[0]);                                  \
        split_pair(xr0.z, xr0.w, v1[1], v2[1]);                                  \
        split_pair(xr1.x, xr1.y, v1[2], v2[2]);                                  \
        split_pair(xr1.z, xr1.w, v1[3], v2[3]);                                  \
        const uint32_t xrb = (uint32_t)xb * ROWB + xq * 16;                      \
        asm volatile("st.shared.v4.b32 [%0], {%1,%2,%3,%4};" ::                  \
            "r"(sb + XS_OFF(buf, 0) + xrb), "r"(v1[0]), "r"(v1[1]), "r"(v1[2]), "r"(v1[3]) : "memory"); \
        asm volatile("st.shared.v4.b32 [%0], {%1,%2,%3,%4};" ::                  \
            "r"(sb + XS_OFF(buf, 1) + xrb), "r"(v2[0]), "r"(v2[1]), "r"(v2[2]), "r"(v2[3]) : "memory"); \
    } while (0)

    // ---- prologue: chunk 0 -> buf 0; prefetch chunk 1 ----
    WLOAD(0); XLOAD(0);
    CONVERT_STAGE(0);
    WLOAD(1); XLOAD(1);

    for (int kc = 0; kc < NCHUNK; kc++) {
        __syncthreads();   // convert(kc) visible to all; prior buf reuse safe

        if (kc + 1 < NCHUNK) {
            CONVERT_STAGE((kc + 1) & 1);            // consumes wr/xr (chunk kc+1)
            if (kc + 2 < NCHUNK) { WLOAD(kc + 2); XLOAD(kc + 2); }  // refill
        }

        // ---- mma on fp16 buf kc&1 ----
        const int cur = kc & 1;
        #pragma unroll
        for (int ks = 0; ks < 2; ks++) {
            uint32_t a1[2][4], a2[2][4];
            #pragma unroll
            for (int m = 0; m < 2; m++) {
                ldsm4(a1[m], sb + XS_OFF(cur, 0) + a_row + (uint32_t)m * (16 * ROWB) + ks * 32);
                ldsm4(a2[m], sb + XS_OFF(cur, 1) + a_row + (uint32_t)m * (16 * ROWB) + ks * 32);
            }
            #pragma unroll
            for (int jp = 0; jp < 4; jp += 2) {
                uint32_t B1[4], B2[4];
                ldsm4(B1, sb + WS_OFF(cur, 0) + b_row4 + (uint32_t)jp * (8 * ROWB) + ks * 32);
                ldsm4(B2, sb + WS_OFF(cur, 1) + b_row4 + (uint32_t)jp * (8 * ROWB) + ks * 32);
                #pragma unroll
                for (int m = 0; m < 2; m++) {
                    mma16816(lo[m][jp],     a1[m], &B1[0]);
                    mma16816(lo[m][jp + 1], a1[m], &B1[2]);
                    mma16816(hi[m][jp],     a1[m], &B2[0]);
                    mma16816(hi[m][jp + 1], a1[m], &B2[2]);
                    mma16816(hi[m][jp],     a2[m], &B1[0]);
                    mma16816(hi[m][jp + 1], a2[m], &B1[2]);
                }
            }
        }
    }

    // ---- epilogue: Y = lo + hi/2048 + bias ----
    const float s = 1.0f / 2048.0f;
    const int ncol = n0 + noct * 32 + (lane & 3) * 2;
    #pragma unroll
    for (int m = 0; m < 2; m++) {
        const int brow = 32 * mpair + 16 * m + (lane >> 2);
        #pragma unroll
        for (int j = 0; j < 4; j++) {
            const int n = ncol + j * 8;
            const float2 bz = *(const float2*)&bias[n];
            float2 o0 = make_float2(fmaf(hi[m][j][0], s, lo[m][j][0]) + bz.x,
                                    fmaf(hi[m][j][1], s, lo[m][j][1]) + bz.y);
            float2 o1 = make_float2(fmaf(hi[m][j][2], s, lo[m][j][2]) + bz.x,
                                    fmaf(hi[m][j][3], s, lo[m][j][3]) + bz.y);
            *(float2*)&g_Y[(size_t)brow * HH + n]       = o0;
            *(float2*)&g_Y[(size_t)(brow + 8) * HH + n] = o1;
        }
    }
    #undef WLOAD
    #undef XLOAD
    #undef CONVERT_STAGE
}

// ---------------- Qpart[s,b,k] = sum_{h in slice s} x[b,h] * Y[b, h*H + k] --
__global__ void contract_q(const float* __restrict__ X) {
    const int b = blockIdx.y, s = blockIdx.x;
    const int k = threadIdx.x;  // 512
    __shared__ float xs[64];
    if (k < 64) xs[k] = X[b * HDIM + s * 64 + k];
    __syncthreads();
    const float* Yb = g_Y + (size_t)b * HH + (size_t)s * 64 * HDIM + k;
    float a0 = 0.f, a1 = 0.f, a2 = 0.f, a3 = 0.f;
    #pragma unroll
    for (int hh = 0; hh < 64; hh += 4) {
        a0 = fmaf(xs[hh + 0], Yb[(hh + 0) * HDIM], a0);
        a1 = fmaf(xs[hh + 1], Yb[(hh + 1) * HDIM], a1);
        a2 = fmaf(xs[hh + 2], Yb[(hh + 2) * HDIM], a2);
        a3 = fmaf(xs[hh + 3], Yb[(hh + 3) * HDIM], a3);
    }
    g_Qp[(s * BATCH + b) * HDIM + k] = (a0 + a1) + (a2 + a3);
}

__global__ void reduce_q() {
    const int b = blockIdx.x, k = threadIdx.x;
    float v = 0.f;
    #pragma unroll
    for (int s = 0; s < 8; s++) v += g_Qp[(s * BATCH + b) * HDIM + k];
    g_Q[b * HDIM + k] = v;
}

// ---------------- w[b,h] = < Y[b, h*H : h*H+H] , Q[b,:] > -------------------
__global__ void contract_w() {
    const int b = blockIdx.y;
    const int warp = threadIdx.x >> 5, lane = threadIdx.x & 31;
    const int h = blockIdx.x * 8 + warp;
    __shared__ float qs[HDIM];
    for (int i = threadIdx.x; i < HDIM; i += 256) qs[i] = g_Q[b * HDIM + i];
    __syncthreads();
    const float* Yb = g_Y + (size_t)b * HH + (size_t)h * HDIM;
    float acc = 0.f;
    #pragma unroll
    for (int s2 = 0; s2 < 4; s2++) {
        const int i4 = lane + s2 * 32;
        float4 y = *(const float4*)&Yb[i4 * 4];
        float4 q = *(const float4*)&qs[i4 * 4];
        acc += y.x * q.x + y.y * q.y + y.z * q.z + y.w * q.w;
    }
    #pragma unroll
    for (int off = 16; off; off >>= 1) acc += __shfl_xor_sync(~0u, acc, off);
    if (lane == 0) g_w[b * HDIM + h] = acc;
}

// ---------------- compat[b,n] = norm * < ve[b,n,:], w[b,:] > ----------------
__global__ void compat_k(const float* __restrict__ ve) {
    const int b = blockIdx.y;
    const int warp = threadIdx.x >> 5, lane = threadIdx.x & 31;
    const int n = blockIdx.x * 8 + warp;
    __shared__ float ws[HDIM];
    for (int i = threadIdx.x; i < HDIM; i += 256) ws[i] = g_w[b * HDIM + i];
    __syncthreads();
    const float* v = ve + ((size_t)b * NSEQ + n) * HDIM;
    float acc = 0.f;
    #pragma unroll
    for (int s2 = 0; s2 < 4; s2++) {
        const int i4 = lane + s2 * 32;
        float4 y = *(const float4*)&v[i4 * 4];
        float4 q = *(const float4*)&ws[i4 * 4];
        acc += y.x * q.x + y.y * q.y + y.z * q.z + y.w * q.w;
    }
    #pragma unroll
    for (int off = 16; off; off >>= 1) acc += __shfl_xor_sync(~0u, acc, off);
    if (lane == 0) g_compat[b * NSEQ + n] = acc * 0.04419417382415922f;
}

// ---------------- per-batch ranking with fp32-exp flush boundary ------------
__global__ __launch_bounds__(1024) void topk_k() {
    __shared__ unsigned sk[NSEQ];
    __shared__ int      si[NSEQ];
    __shared__ float    redf[32];
    const int b = blockIdx.x, t = threadIdx.x;
    const int lane = t & 31, warp = t >> 5;

    const float c0 = g_compat[b * NSEQ + t];
    const float c1 = g_compat[b * NSEQ + t + 1024];

    float m = fmaxf(c0, c1);
    #pragma unroll
    for (int o = 16; o; o >>= 1) m = fmaxf(m, __shfl_xor_sync(~0u, m, o));
    if (lane == 0) redf[warp] = m;
    __syncthreads();
    float mx = redf[0];
    #pragma unroll
    for (int i = 1; i < 32; i++) mx = fmaxf(mx, redf[i]);

    auto mkkey = [&](float c) -> unsigned {
        float d = c - mx;
        if (d < -87.33654785f) return 0u;
        unsigned u = __float_as_uint(c);
        return (u & 0x80000000u) ? ~u : (u | 0x80000000u);
    };
    sk[t]        = mkkey(c0);  si[t]        = t;
    sk[t + 1024] = mkkey(c1);  si[t + 1024] = t + 1024;

    for (int k = 2; k <= NSEQ; k <<= 1) {
        for (int j = k >> 1; j > 0; j >>= 1) {
            __syncthreads();
            #pragma unroll
            for (int half = 0; half < 2; half++) {
                const int i = half * 1024 + t;
                const int ixj = i ^ j;
                if (ixj > i) {
                    const bool desc = ((i & k) == 0);
                    unsigned ki = sk[i], kj = sk[ixj];
                    int      ii = si[i], ij = si[ixj];
                    const bool jBeforeI = (kj > ki) || (kj == ki && ij < ii);
                    if (desc ? jBeforeI : !jBeforeI) {
                        sk[i] = kj; sk[ixj] = ki;
                        si[i] = ij; si[ixj] = ii;
                    }
                }
            }
        }
    }
    __syncthreads();
    if (t < NFOCUS) g_idx[b * NFOCUS + t] = si[t];
}

// ---------------- gather: out[b,r,:] = ve[b, idx[b,r], :] -------------------
__global__ void gather_k(const float* __restrict__ ve, float* __restrict__ out) {
    const int b = blockIdx.y, r = blockIdx.x;
    const int idx = g_idx[b * NFOCUS + r];
    const float4* src = (const float4*)(ve + ((size_t)b * NSEQ + idx) * HDIM);
    float4* dst = (float4*)(out + ((size_t)b * NFOCUS + r) * HDIM);
    dst[threadIdx.x] = src[threadIdx.x];
}

// ---------------- launch ----------------------------------------------------
extern "C" void kernel_launch(void* const* d_in, const int* in_sizes, int n_in,
                              void* d_out, int out_size) {
    const float* vs = (const float*)d_in[0];   // (64, 1, 512)
    const float* ve = (const float*)d_in[1];   // (64, 2048, 512)
    const float* Wq = (const float*)d_in[2];   // (512, 262144)
    const float* bq = (const float*)d_in[3];   // (262144,)
    const float* Wk = (const float*)d_in[4];   // (512, 262144)
    const float* bk = (const float*)d_in[5];   // (262144,)
    float* out = (float*)d_out;                // (64, 256, 512)

    cudaFuncSetAttribute(gemm_mma, cudaFuncAttributeMaxDynamicSharedMemorySize, SMEM_BYTES);

    gemm_mma<<<HH / NTILE, THREADS, SMEM_BYTES>>>(vs, Wq, bq);
    contract_q<<<dim3(8, BATCH), 512>>>(vs);
    reduce_q<<<BATCH, HDIM>>>();

    gemm_mma<<<HH / NTILE, THREADS, SMEM_BYTES>>>(vs, Wk, bk);
    contract_w<<<dim3(64, BATCH), 256>>>();

    compat_k<<<dim3(NSEQ / 8, BATCH), 256>>>(ve);
    topk_k<<<BATCH, 1024>>>();
    gather_k<<<dim3(NFOCUS, BATCH), 128>>>(ve, out);
}

// round 16
// speedup vs baseline: 1.7689x; 1.0214x over previous
#include <cuda_runtime.h>
#include <cuda_fp16.h>
#include <cstdint>

#define BATCH 64
#define HDIM 512
#define HH 262144      // HDIM*HDIM
#define NSEQ 2048
#define NFOCUS 256

// ---------------- scratch (static device globals; no runtime allocation) ----
__device__ float g_Y[(size_t)BATCH * HH];      // 64 MB (Yq then Yk)
__device__ float g_Qp[8 * BATCH * HDIM];
__device__ float g_Q[BATCH * HDIM];
__device__ float g_w[BATCH * HDIM];
__device__ float g_compat[BATCH * NSEQ];
__device__ int   g_idx[BATCH * NFOCUS];

// ======================= mma.sync helpers (HMMA path) =======================
__device__ __forceinline__ uint32_t smem_u32(const void* p) {
    uint32_t a;
    asm("{ .reg .u64 t; cvta.to.shared.u64 t, %1; cvt.u32.u64 %0, t; }"
        : "=r"(a) : "l"(p));
    return a;
}
__device__ __forceinline__ void ldsm4(uint32_t* r, uint32_t a) {
    asm volatile("ldmatrix.sync.aligned.m8n8.x4.shared.b16 {%0,%1,%2,%3}, [%4];"
                 : "=r"(r[0]), "=r"(r[1]), "=r"(r[2]), "=r"(r[3]) : "r"(a));
}
__device__ __forceinline__ void mma16816(float* c, const uint32_t* a, const uint32_t* b) {
    asm volatile(
        "mma.sync.aligned.m16n8k16.row.col.f32.f16.f16.f32 "
        "{%0,%1,%2,%3}, {%4,%5,%6,%7}, {%8,%9}, {%0,%1,%2,%3};"
        : "+f"(c[0]), "+f"(c[1]), "+f"(c[2]), "+f"(c[3])
        : "r"(a[0]), "r"(a[1]), "r"(a[2]), "r"(a[3]), "r"(b[0]), "r"(b[1]));
}
// Split a PAIR of fp32 into two packed fp16 levels with only 2 cvt instrs.
__device__ __forceinline__ void split_pair(float x0, float x1,
                                           uint32_t& uA, uint32_t& uB) {
    uint32_t b0 = __float_as_uint(x0), b1 = __float_as_uint(x1);
    float t0 = __uint_as_float((b0 + 0xFFFu + ((b0 >> 13) & 1u)) & 0xFFFFE000u);
    float t1 = __uint_as_float((b1 + 0xFFFu + ((b1 >> 13) & 1u)) & 0xFFFFE000u);
    float r0 = (x0 - t0) * 2048.0f;
    float r1 = (x1 - t1) * 2048.0f;
    asm("cvt.rn.f16x2.f32 %0, %1, %2;" : "=r"(uA) : "f"(t1), "f"(t0));
    asm("cvt.rn.f16x2.f32 %0, %1, %2;" : "=r"(uB) : "f"(r1), "f"(r0));
}

// ========= emulated-fp32 GEMM via 2-way fp16 split (3 HMMA products) ========
// 2 CTAs/SM. No raw smem ring: W streamed gmem -> regs (1-chunk prefetch,
// single 16-reg buffer) -> split -> fp16 STS. X likewise (8 regs). One
// __syncthreads per chunk. B fragments via ldsm4 (2 j-groups per instr).
#define KC 32                        // k per chunk
#define NCHUNK (HDIM / KC)           // 16
#define NTILE 128                    // n per CTA
#define THREADS 256
#define ROWB 80                      // padded fp16 smem row bytes (64B + 16 pad)
// smem byte offsets (fp16 double-buffer only):
#define WS_OFF(buf, lvl)  ((buf) * 30720u + (lvl) * 10240u)           // 128n x 32k
#define XS_OFF(buf, lvl)  ((buf) * 30720u + 20480u + (lvl) * 5120u)   // 64b x 32k
#define SMEM_BYTES 61440

__global__ __launch_bounds__(THREADS, 2) void gemm_mma(
    const float* __restrict__ X, const float* __restrict__ W,
    const float* __restrict__ bias)
{
    extern __shared__ __align__(16) char smem_raw[];
    const uint32_t sb = smem_u32(smem_raw);
    const int tid = threadIdx.x;
    const int wid = tid >> 5, lane = tid & 31;
    const int n0 = blockIdx.x * NTILE;

    // warp tile: 32 batches (mpair) x 32 n (noct 0..3)
    const int mpair = wid & 1;
    const int noct  = wid >> 1;

    float lo[2][4][4], hi[2][4][4];
    #pragma unroll
    for (int m = 0; m < 2; m++)
        #pragma unroll
        for (int j = 0; j < 4; j++)
            #pragma unroll
            for (int q = 0; q < 4; q++) { lo[m][j][q] = 0.f; hi[m][j][q] = 0.f; }

    // converter mappings (256 threads)
    const int wn = tid & 127, wkh = tid >> 7;     // W: n col, k-half (16k each)
    const int xb = tid >> 2, xq = tid & 3;        // X: batch row, k-octet(8)

    // register prefetch buffers (single-buffer, 1 chunk ahead)
    float  wr[16];
    float4 xr0, xr1;

    // fragment smem base offsets
    const uint32_t a_row  = (uint32_t)(32 * mpair + (lane & 15)) * ROWB + ((lane >> 4) << 4);
    // B ldsm4: lanes 0-7 -> rows n0..n0+7 khalf0; 8-15 khalf1; 16-31 same at +8 rows
    const uint32_t b_row4 = (uint32_t)(noct * 32 + (lane & 7) + ((lane >> 4) << 3)) * ROWB
                          + (((lane >> 3) & 1) << 4);

    #define WLOAD(chunk) do {                                                    \
        const float* wsrc = W + (size_t)((chunk) * KC + wkh * 16) * HH + n0 + wn;\
        _Pragma("unroll")                                                        \
        for (int j = 0; j < 16; j++)                                             \
            wr[j] = __ldcs(wsrc + (size_t)j * HH);                               \
    } while (0)

    #define XLOAD(chunk) do {                                                    \
        const float* xsrc = X + (size_t)xb * HDIM + (chunk) * KC + xq * 8;       \
        xr0 = __ldg((const float4*)xsrc);                                        \
        xr1 = __ldg((const float4*)(xsrc + 4));                                  \
    } while (0)

    #define CONVERT_STAGE(buf) do {                                              \
        uint32_t u1[8], u2[8];                                                   \
        _Pragma("unroll")                                                        \
        for (int p = 0; p < 8; p++)                                              \
            split_pair(wr[2 * p], wr[2 * p + 1], u1[p], u2[p]);                  \
        const uint32_t rb = (uint32_t)wn * ROWB + wkh * 32;                      \
        asm volatile("st.shared.v4.b32 [%0], {%1,%2,%3,%4};" ::                  \
            "r"(sb + WS_OFF(buf, 0) + rb), "r"(u1[0]), "r"(u1[1]), "r"(u1[2]), "r"(u1[3]) : "memory"); \
        asm volatile("st.shared.v4.b32 [%0], {%1,%2,%3,%4};" ::                  \
            "r"(sb + WS_OFF(buf, 0) + rb + 16), "r"(u1[4]), "r"(u1[5]), "r"(u1[6]), "r"(u1[7]) : "memory"); \
        asm volatile("st.shared.v4.b32 [%0], {%1,%2,%3,%4};" ::                  \
            "r"(sb + WS_OFF(buf, 1) + rb), "r"(u2[0]), "r"(u2[1]), "r"(u2[2]), "r"(u2[3]) : "memory"); \
        asm volatile("st.shared.v4.b32 [%0], {%1,%2,%3,%4};" ::                  \
            "r"(sb + WS_OFF(buf, 1) + rb + 16), "r"(u2[4]), "r"(u2[5]), "r"(u2[6]), "r"(u2[7]) : "memory"); \
        uint32_t v1[4], v2[4];                                                   \
        split_pair(xr0.x, xr0.y, v1[0], v2[0]);                                  \
        split_pair(xr0.z, xr0.w, v1[1], v2[1]);                                  \
        split_pair(xr1.x, xr1.y, v1[2], v2[2]);                                  \
        split_pair(xr1.z, xr1.w, v1[3], v2[3]);                                  \
        const uint32_t xrb = (uint32_t)xb * ROWB + xq * 16;                      \
        asm volatile("st.shared.v4.b32 [%0], {%1,%2,%3,%4};" ::                  \
            "r"(sb + XS_OFF(buf, 0) + xrb), "r"(v1[0]), "r"(v1[1]), "r"(v1[2]), "r"(v1[3]) : "memory"); \
        asm volatile("st.shared.v4.b32 [%0], {%1,%2,%3,%4};" ::                  \
            "r"(sb + XS_OFF(buf, 1) + xrb), "r"(v2[0]), "r"(v2[1]), "r"(v2[2]), "r"(v2[3]) : "memory"); \
    } while (0)

    // ---- prologue: chunk 0 -> buf 0; prefetch chunk 1 ----
    WLOAD(0); XLOAD(0);
    CONVERT_STAGE(0);
    WLOAD(1); XLOAD(1);

    for (int kc = 0; kc < NCHUNK; kc++) {
        __syncthreads();   // convert(kc) visible to all; prior buf reuse safe

        if (kc + 1 < NCHUNK) {
            CONVERT_STAGE((kc + 1) & 1);            // consumes wr/xr (chunk kc+1)
            if (kc + 2 < NCHUNK) { WLOAD(kc + 2); XLOAD(kc + 2); }  // refill
        }

        // ---- mma on fp16 buf kc&1 ----
        const int cur = kc & 1;
        #pragma unroll
        for (int ks = 0; ks < 2; ks++) {
            uint32_t a1[2][4], a2[2][4];
            #pragma unroll
            for (int m = 0; m < 2; m++) {
                ldsm4(a1[m], sb + XS_OFF(cur, 0) + a_row + (uint32_t)m * (16 * ROWB) + ks * 32);
                ldsm4(a2[m], sb + XS_OFF(cur, 1) + a_row + (uint32_t)m * (16 * ROWB) + ks * 32);
            }
            #pragma unroll
            for (int jp = 0; jp < 4; jp += 2) {
                uint32_t B1[4], B2[4];
                ldsm4(B1, sb + WS_OFF(cur, 0) + b_row4 + (uint32_t)jp * (8 * ROWB) + ks * 32);
                ldsm4(B2, sb + WS_OFF(cur, 1) + b_row4 + (uint32_t)jp * (8 * ROWB) + ks * 32);
                #pragma unroll
                for (int m = 0; m < 2; m++) {
                    mma16816(lo[m][jp],     a1[m], &B1[0]);
                    mma16816(lo[m][jp + 1], a1[m], &B1[2]);
                    mma16816(hi[m][jp],     a1[m], &B2[0]);
                    mma16816(hi[m][jp + 1], a1[m], &B2[2]);
                    mma16816(hi[m][jp],     a2[m], &B1[0]);
                    mma16816(hi[m][jp + 1], a2[m], &B1[2]);
                }
            }
        }
    }

    // ---- epilogue: Y = lo + hi/2048 + bias ----
    const float s = 1.0f / 2048.0f;
    const int ncol = n0 + noct * 32 + (lane & 3) * 2;
    #pragma unroll
    for (int m = 0; m < 2; m++) {
        const int brow = 32 * mpair + 16 * m + (lane >> 2);
        #pragma unroll
        for (int j = 0; j < 4; j++) {
            const int n = ncol + j * 8;
            const float2 bz = *(const float2*)&bias[n];
            float2 o0 = make_float2(fmaf(hi[m][j][0], s, lo[m][j][0]) + bz.x,
                                    fmaf(hi[m][j][1], s, lo[m][j][1]) + bz.y);
            float2 o1 = make_float2(fmaf(hi[m][j][2], s, lo[m][j][2]) + bz.x,
                                    fmaf(hi[m][j][3], s, lo[m][j][3]) + bz.y);
            *(float2*)&g_Y[(size_t)brow * HH + n]       = o0;
            *(float2*)&g_Y[(size_t)(brow + 8) * HH + n] = o1;
        }
    }
    #undef WLOAD
    #undef XLOAD
    #undef CONVERT_STAGE
}

// ---------------- Qpart[s,b,k] = sum_{h in slice s} x[b,h] * Y[b, h*H + k] --
__global__ void contract_q(const float* __restrict__ X) {
    const int b = blockIdx.y, s = blockIdx.x;
    const int k = threadIdx.x;  // 512
    __shared__ float xs[64];
    if (k < 64) xs[k] = X[b * HDIM + s * 64 + k];
    __syncthreads();
    const float* Yb = g_Y + (size_t)b * HH + (size_t)s * 64 * HDIM + k;
    float a0 = 0.f, a1 = 0.f, a2 = 0.f, a3 = 0.f;
    #pragma unroll
    for (int hh = 0; hh < 64; hh += 4) {
        a0 = fmaf(xs[hh + 0], __ldcs(&Yb[(hh + 0) * HDIM]), a0);
        a1 = fmaf(xs[hh + 1], __ldcs(&Yb[(hh + 1) * HDIM]), a1);
        a2 = fmaf(xs[hh + 2], __ldcs(&Yb[(hh + 2) * HDIM]), a2);
        a3 = fmaf(xs[hh + 3], __ldcs(&Yb[(hh + 3) * HDIM]), a3);
    }
    g_Qp[(s * BATCH + b) * HDIM + k] = (a0 + a1) + (a2 + a3);
}

__global__ void reduce_q() {
    const int b = blockIdx.x, k = threadIdx.x;
    float v = 0.f;
    #pragma unroll
    for (int s = 0; s < 8; s++) v += g_Qp[(s * BATCH + b) * HDIM + k];
    g_Q[b * HDIM + k] = v;
}

// ---------------- w[b,h] = < Y[b, h*H : h*H+H] , Q[b,:] > -------------------
__global__ void contract_w() {
    const int b = blockIdx.y;
    const int warp = threadIdx.x >> 5, lane = threadIdx.x & 31;
    const int h = blockIdx.x * 8 + warp;
    __shared__ float qs[HDIM];
    for (int i = threadIdx.x; i < HDIM; i += 256) qs[i] = g_Q[b * HDIM + i];
    __syncthreads();
    const float* Yb = g_Y + (size_t)b * HH + (size_t)h * HDIM;
    float acc = 0.f;
    #pragma unroll
    for (int s2 = 0; s2 < 4; s2++) {
        const int i4 = lane + s2 * 32;
        float4 y = __ldcs((const float4*)&Yb[i4 * 4]);
        float4 q = *(const float4*)&qs[i4 * 4];
        acc += y.x * q.x + y.y * q.y + y.z * q.z + y.w * q.w;
    }
    #pragma unroll
    for (int off = 16; off; off >>= 1) acc += __shfl_xor_sync(~0u, acc, off);
    if (lane == 0) g_w[b * HDIM + h] = acc;
}

// ---------------- compat[b,n] = norm * < ve[b,n,:], w[b,:] > ----------------
// 2 rows per warp, interleaved streaming loads (MLP 8), per-row order preserved.
__global__ void compat_k(const float* __restrict__ ve) {
    const int b = blockIdx.y;
    const int warp = threadIdx.x >> 5, lane = threadIdx.x & 31;
    const int n = blockIdx.x * 16 + warp * 2;
    __shared__ float ws[HDIM];
    for (int i = threadIdx.x; i < HDIM; i += 256) ws[i] = g_w[b * HDIM + i];
    __syncthreads();
    const float* v0 = ve + ((size_t)b * NSEQ + n) * HDIM;
    const float* v1 = v0 + HDIM;
    float acc0 = 0.f, acc1 = 0.f;
    #pragma unroll
    for (int s2 = 0; s2 < 4; s2++) {
        const int i4 = (lane + s2 * 32) * 4;
        float4 q  = *(const float4*)&ws[i4];
        float4 y0 = __ldcs((const float4*)&v0[i4]);
        float4 y1 = __ldcs((const float4*)&v1[i4]);
        acc0 += y0.x * q.x + y0.y * q.y + y0.z * q.z + y0.w * q.w;
        acc1 += y1.x * q.x + y1.y * q.y + y1.z * q.z + y1.w * q.w;
    }
    #pragma unroll
    for (int off = 16; off; off >>= 1) {
        acc0 += __shfl_xor_sync(~0u, acc0, off);
        acc1 += __shfl_xor_sync(~0u, acc1, off);
    }
    if (lane == 0) {
        g_compat[b * NSEQ + n]     = acc0 * 0.04419417382415922f;
        g_compat[b * NSEQ + n + 1] = acc1 * 0.04419417382415922f;
    }
}

// ---------------- per-batch ranking with fp32-exp flush boundary ------------
__global__ __launch_bounds__(1024) void topk_k() {
    __shared__ unsigned sk[NSEQ];
    __shared__ int      si[NSEQ];
    __shared__ float    redf[32];
    const int b = blockIdx.x, t = threadIdx.x;
    const int lane = t & 31, warp = t >> 5;

    const float c0 = g_compat[b * NSEQ + t];
    const float c1 = g_compat[b * NSEQ + t + 1024];

    float m = fmaxf(c0, c1);
    #pragma unroll
    for (int o = 16; o; o >>= 1) m = fmaxf(m, __shfl_xor_sync(~0u, m, o));
    if (lane == 0) redf[warp] = m;
    __syncthreads();
    float mx = redf[0];
    #pragma unroll
    for (int i = 1; i < 32; i++) mx = fmaxf(mx, redf[i]);

    auto mkkey = [&](float c) -> unsigned {
        float d = c - mx;
        if (d < -87.33654785f) return 0u;
        unsigned u = __float_as_uint(c);
        return (u & 0x80000000u) ? ~u : (u | 0x80000000u);
    };
    sk[t]        = mkkey(c0);  si[t]        = t;
    sk[t + 1024] = mkkey(c1);  si[t + 1024] = t + 1024;

    for (int k = 2; k <= NSEQ; k <<= 1) {
        for (int j = k >> 1; j > 0; j >>= 1) {
            __syncthreads();
            #pragma unroll
            for (int half = 0; half < 2; half++) {
                const int i = half * 1024 + t;
                const int ixj = i ^ j;
                if (ixj > i) {
                    const bool desc = ((i & k) == 0);
                    unsigned ki = sk[i], kj = sk[ixj];
                    int      ii = si[i], ij = si[ixj];
                    const bool jBeforeI = (kj > ki) || (kj == ki && ij < ii);
                    if (desc ? jBeforeI : !jBeforeI) {
                        sk[i] = kj; sk[ixj] = ki;
                        si[i] = ij; si[ixj] = ii;
                    }
                }
            }
        }
    }
    __syncthreads();
    if (t < NFOCUS) g_idx[b * NFOCUS + t] = si[t];
}

// ---------------- gather: out[b,r,:] = ve[b, idx[b,r], :] -------------------
__global__ void gather_k(const float* __restrict__ ve, float* __restrict__ out) {
    const int b = blockIdx.y, r = blockIdx.x;
    const int idx = g_idx[b * NFOCUS + r];
    const float4* src = (const float4*)(ve + ((size_t)b * NSEQ + idx) * HDIM);
    float4* dst = (float4*)(out + ((size_t)b * NFOCUS + r) * HDIM);
    dst[threadIdx.x] = src[threadIdx.x];
}

// ---------------- launch ----------------------------------------------------
extern "C" void kernel_launch(void* const* d_in, const int* in_sizes, int n_in,
                              void* d_out, int out_size) {
    const float* vs = (const float*)d_in[0];   // (64, 1, 512)
    const float* ve = (const float*)d_in[1];   // (64, 2048, 512)
    const float* Wq = (const float*)d_in[2];   // (512, 262144)
    const float* bq = (const float*)d_in[3];   // (262144,)
    const float* Wk = (const float*)d_in[4];   // (512, 262144)
    const float* bk = (const float*)d_in[5];   // (262144,)
    float* out = (float*)d_out;                // (64, 256, 512)

    cudaFuncSetAttribute(gemm_mma, cudaFuncAttributeMaxDynamicSharedMemorySize, SMEM_BYTES);

    gemm_mma<<<HH / NTILE, THREADS, SMEM_BYTES>>>(vs, Wq, bq);
    contract_q<<<dim3(8, BATCH), 512>>>(vs);
    reduce_q<<<BATCH, HDIM>>>();

    gemm_mma<<<HH / NTILE, THREADS, SMEM_BYTES>>>(vs, Wk, bk);
    contract_w<<<dim3(64, BATCH), 256>>>();

    compat_k<<<dim3(NSEQ / 16, BATCH), 256>>>(ve);
    topk_k<<<BATCH, 1024>>>();
    gather_k<<<dim3(NFOCUS, BATCH), 128>>>(ve, out);
}